// round 8
// baseline (speedup 1.0000x reference)
#include <cuda_runtime.h>
#include <cuda_fp16.h>
#include <math.h>
#include <stdint.h>

#define B_  4
#define T_  24
#define N_  2048
#define D_  256
#define H_  8
#define HD_ 32
#define MTOK (B_*T_*N_)           // 196608 tokens
#define ELEMS ((size_t)MTOK * D_) // 50,331,648

// Scratch (device globals; allocation-free per harness rules). All fp16.
__device__ __half g_q [ELEMS];
__device__ __half g_k [ELEMS];
__device__ __half g_v [ELEMS];
__device__ __half g_os[ELEMS];
__device__ __half g_ot[ELEMS];
__device__ __half g_wqh[768*256];
__device__ __half g_woh[256*512];

// ---------------------------------------------------------------------------
// helpers
// ---------------------------------------------------------------------------
__device__ __forceinline__ uint32_t smem_u32(const void* p) {
    uint32_t a;
    asm("{ .reg .u64 t; cvta.to.shared.u64 t, %1; cvt.u32.u64 %0, t; }"
        : "=r"(a) : "l"(p));
    return a;
}
__device__ __forceinline__ uint32_t f2h2(float a, float b) {
    __half2 h = __floats2half2_rn(a, b);
    return *(uint32_t*)&h;
}
__device__ __forceinline__ uint2 f4h(float4 v) {
    return make_uint2(f2h2(v.x, v.y), f2h2(v.z, v.w));
}
__device__ __forceinline__ float2 h2f2(uint32_t h) {
    return __half22float2(*(__half2*)&h);
}
__device__ __forceinline__ void ldm_x4(uint32_t* r, uint32_t addr) {
    asm volatile("ldmatrix.sync.aligned.m8n8.x4.shared.b16 {%0,%1,%2,%3}, [%4];"
                 : "=r"(r[0]), "=r"(r[1]), "=r"(r[2]), "=r"(r[3]) : "r"(addr));
}
#define MMA_F16(d, a0, a1, a2, a3, b0, b1)                                    \
    asm volatile("mma.sync.aligned.m16n8k16.row.col.f32.f16.f16.f32 "         \
                 "{%0,%1,%2,%3}, {%4,%5,%6,%7}, {%8,%9}, {%0,%1,%2,%3};"      \
                 : "+f"(d[0]), "+f"(d[1]), "+f"(d[2]), "+f"(d[3])             \
                 : "r"(a0), "r"(a1), "r"(a2), "r"(a3), "r"(b0), "r"(b1))

// ---- packed fp32x2 (Blackwell FFMA2) ----
__device__ __forceinline__ uint64_t pk2(float x, float y) {
    uint64_t r;
    asm("mov.b64 %0, {%1,%2};" : "=l"(r) : "f"(x), "f"(y));
    return r;
}
__device__ __forceinline__ uint64_t bc2(float x) { return pk2(x, x); }
__device__ __forceinline__ float2 upk2(uint64_t v) {
    float2 f;
    asm("mov.b64 {%0,%1}, %2;" : "=f"(f.x), "=f"(f.y) : "l"(v));
    return f;
}
#define FFMA2(d, a, b) \
    asm("fma.rn.f32x2 %0, %1, %2, %0;" : "+l"(d) : "l"(a), "l"(b))

// Row strides: 80B (chunk tiles) and 528B (resident A). Both ≡16 (mod 128).
#define CH_STRIDE 80
#define CH_BYTES  (128*CH_STRIDE)
#define AR_STRIDE 528
#define AR_BYTES  (128*AR_STRIDE)

// ---------------------------------------------------------------------------
// weight pre-conversion: f32 -> f16 (once per launch)
// ---------------------------------------------------------------------------
__global__ void cvt_weights_kernel(const float* __restrict__ wq,
                                   const float* __restrict__ wo,
                                   __half* __restrict__ wqh,
                                   __half* __restrict__ woh)
{
    int i = blockIdx.x * blockDim.x + threadIdx.x;
    const int NQ = 768 * 256 / 2;
    const int NO = 256 * 512 / 2;
    if (i < NQ) {
        float2 f = *(const float2*)(wq + i * 2);
        *(uint32_t*)(wqh + i * 2) = f2h2(f.x, f.y);
    } else if (i < NQ + NO) {
        int j = i - NQ;
        float2 f = *(const float2*)(wo + j * 2);
        *(uint32_t*)(woh + j * 2) = f2h2(f.x, f.y);
    }
}

// ===========================================================================
// GEMM1 (A-resident, fp16): qkv[M,768] = x[M,256] * w_qkv[768,256]^T
// ===========================================================================
#define G1_SMEM (AR_BYTES + 2*CH_BYTES)   // 88064

__global__ __launch_bounds__(256, 2)
void gemm_qkv_kernel(const float* __restrict__ A, const __half* __restrict__ Bw,
                     __half* __restrict__ outq, __half* __restrict__ outk,
                     __half* __restrict__ outv)
{
    extern __shared__ __align__(16) char smem[];
    const uint32_t sbase = smem_u32(smem);
    const int tid  = threadIdx.x;
    const int lane = tid & 31;
    const int wid  = tid >> 5;
    const int wm   = wid & 1;
    const int wn   = wid >> 1;
    const int m0   = blockIdx.x * 128;

    const int ar = tid >> 1;
    const int ac = tid & 1;
    const int fr = lane & 15;
    const int fc = (lane >> 4) * 16;
    const int r  = lane >> 2;
    const int c2 = (lane & 3) << 1;

    #pragma unroll
    for (int j = 0; j < 8; j++) {
        const float* ap = A + (size_t)(m0 + ar) * 256 + (ac * 8 + j) * 16;
        uint2 h0 = f4h(*(const float4*)(ap + 0));
        uint2 h1 = f4h(*(const float4*)(ap + 4));
        uint2 h2 = f4h(*(const float4*)(ap + 8));
        uint2 h3 = f4h(*(const float4*)(ap + 12));
        char* dst = smem + ar * AR_STRIDE + (ac * 8 + j) * 32;
        *(uint4*)(dst)      = make_uint4(h0.x, h0.y, h1.x, h1.y);
        *(uint4*)(dst + 16) = make_uint4(h2.x, h2.y, h3.x, h3.y);
    }

    uint4 hb0, hb1;
    auto ldgB = [&](int it) {
        const int nt = it >> 3, kt = it & 7;
        const __half* bp = Bw + (size_t)(nt * 128 + ar) * 256 + kt * 32 + ac * 16;
        hb0 = *(const uint4*)(bp);
        hb1 = *(const uint4*)(bp + 8);
    };
    auto stsB = [&](int buf) {
        char* dst = smem + AR_BYTES + buf * CH_BYTES + ar * CH_STRIDE + ac * 32;
        *(uint4*)(dst)      = hb0;
        *(uint4*)(dst + 16) = hb1;
    };

    float acc[4][4][4];
    #pragma unroll
    for (int i = 0; i < 4; i++)
        #pragma unroll
        for (int j = 0; j < 4; j++)
            #pragma unroll
            for (int c = 0; c < 4; c++) acc[i][j][c] = 0.f;

    ldgB(0);
    stsB(0);
    __syncthreads();

    #pragma unroll 1
    for (int it = 0; it < 48; it++) {
        if (it + 1 < 48) ldgB(it + 1);

        {
            const int kt = it & 7;
            const uint32_t abase = sbase + kt * 64;
            const uint32_t bbase = sbase + AR_BYTES + (it & 1) * CH_BYTES;
            #pragma unroll
            for (int s = 0; s < 2; s++) {
                uint32_t af[4][4], bf[2][4];
                #pragma unroll
                for (int mt = 0; mt < 4; mt++) {
                    int row = wm * 64 + mt * 16 + fr;
                    ldm_x4(af[mt], abase + row * AR_STRIDE + s * 32 + fc);
                }
                #pragma unroll
                for (int bi = 0; bi < 2; bi++) {
                    int row = wn * 32 + bi * 16 + fr;
                    ldm_x4(bf[bi], bbase + row * CH_STRIDE + s * 32 + fc);
                }
                #pragma unroll
                for (int mt = 0; mt < 4; mt++)
                    #pragma unroll
                    for (int nt2 = 0; nt2 < 4; nt2++) {
                        int bi = nt2 >> 1, od = nt2 & 1;
                        MMA_F16(acc[mt][nt2],
                                af[mt][0], af[mt][1], af[mt][2], af[mt][3],
                                bf[bi][od], bf[bi][od + 2]);
                    }
            }
        }

        if ((it & 7) == 7) {
            const int n0g = (it >> 3) * 128;
            const int sel = n0g >> 8;

            if (sel < 2) {
                #pragma unroll
                for (int mt = 0; mt < 4; mt++) {
                    float sslo = 0.f, sshi = 0.f;
                    #pragma unroll
                    for (int nt2 = 0; nt2 < 4; nt2++) {
                        sslo = fmaf(acc[mt][nt2][0], acc[mt][nt2][0], sslo);
                        sslo = fmaf(acc[mt][nt2][1], acc[mt][nt2][1], sslo);
                        sshi = fmaf(acc[mt][nt2][2], acc[mt][nt2][2], sshi);
                        sshi = fmaf(acc[mt][nt2][3], acc[mt][nt2][3], sshi);
                    }
                    sslo += __shfl_xor_sync(0xffffffffu, sslo, 1);
                    sslo += __shfl_xor_sync(0xffffffffu, sslo, 2);
                    sshi += __shfl_xor_sync(0xffffffffu, sshi, 1);
                    sshi += __shfl_xor_sync(0xffffffffu, sshi, 2);
                    float slo = 1.f / fmaxf(sqrtf(sslo), 1e-12f);
                    float shi = 1.f / fmaxf(sqrtf(sshi), 1e-12f);
                    #pragma unroll
                    for (int nt2 = 0; nt2 < 4; nt2++) {
                        acc[mt][nt2][0] *= slo; acc[mt][nt2][1] *= slo;
                        acc[mt][nt2][2] *= shi; acc[mt][nt2][3] *= shi;
                    }
                }
            }

            __half* dst = (sel == 0) ? outq : ((sel == 1) ? outk : outv);
            #pragma unroll
            for (int mt = 0; mt < 4; mt++) {
                int m = m0 + wm * 64 + mt * 16 + r;
                #pragma unroll
                for (int nt2 = 0; nt2 < 4; nt2++) {
                    int col = ((n0g + wn * 32 + nt2 * 8 + c2) & 255);
                    float* a = acc[mt][nt2];
                    *(uint32_t*)(dst + (size_t)m * 256 + col)       = f2h2(a[0], a[1]);
                    *(uint32_t*)(dst + (size_t)(m + 8) * 256 + col) = f2h2(a[2], a[3]);
                    a[0] = a[1] = a[2] = a[3] = 0.f;
                }
            }
        }

        if (it + 1 < 48) stsB((it + 1) & 1);
        __syncthreads();
    }
}

// ===========================================================================
// GEMM2 (fp16 in / f32 out): out = [os|ot] * w_out^T + b
// ===========================================================================
#define G2_SMEM (4*CH_BYTES)   // 40960

__global__ __launch_bounds__(256, 2)
void gemm_out_kernel(const __half* __restrict__ A0, const __half* __restrict__ A1,
                     const __half* __restrict__ Bw,
                     const float* __restrict__ bias,
                     float* __restrict__ out)
{
    extern __shared__ __align__(16) char smem[];
    const uint32_t sbase = smem_u32(smem);
    const int tid  = threadIdx.x;
    const int lane = tid & 31;
    const int wid  = tid >> 5;
    const int wm   = wid & 1;
    const int wn   = wid >> 1;
    const int m0   = blockIdx.y * 128;
    const int n0g  = blockIdx.x * 128;

    const int ar = tid >> 1;
    const int ac = tid & 1;
    const int fr = lane & 15;
    const int fc = (lane >> 4) * 16;
    const int r  = lane >> 2;
    const int c2 = (lane & 3) << 1;

    uint4 ua0, ua1, ub0, ub1;
    auto ldg = [&](int kt) {
        const int k0 = kt * 32;
        const __half* Asrc = (k0 < 256) ? A0 : A1;
        const int kc = k0 & 255;
        const __half* ap = Asrc + (size_t)(m0 + ar) * 256 + kc + ac * 16;
        ua0 = *(const uint4*)(ap);
        ua1 = *(const uint4*)(ap + 8);
        const __half* bp = Bw + (size_t)(n0g + ar) * 512 + k0 + ac * 16;
        ub0 = *(const uint4*)(bp);
        ub1 = *(const uint4*)(bp + 8);
    };
    auto sts = [&](int buf) {
        char* da = smem + buf * 2 * CH_BYTES + ar * CH_STRIDE + ac * 32;
        *(uint4*)(da)      = ua0;
        *(uint4*)(da + 16) = ua1;
        char* db = da + CH_BYTES;
        *(uint4*)(db)      = ub0;
        *(uint4*)(db + 16) = ub1;
    };

    float acc[4][4][4];
    #pragma unroll
    for (int i = 0; i < 4; i++)
        #pragma unroll
        for (int j = 0; j < 4; j++)
            #pragma unroll
            for (int c = 0; c < 4; c++) acc[i][j][c] = 0.f;

    ldg(0);
    sts(0);
    __syncthreads();

    #pragma unroll 1
    for (int kt = 0; kt < 16; kt++) {
        if (kt + 1 < 16) ldg(kt + 1);

        {
            const uint32_t abase = sbase + (kt & 1) * 2 * CH_BYTES;
            const uint32_t bbase = abase + CH_BYTES;
            #pragma unroll
            for (int s = 0; s < 2; s++) {
                uint32_t af[4][4], bf[2][4];
                #pragma unroll
                for (int mt = 0; mt < 4; mt++) {
                    int row = wm * 64 + mt * 16 + fr;
                    ldm_x4(af[mt], abase + row * CH_STRIDE + s * 32 + fc);
                }
                #pragma unroll
                for (int bi = 0; bi < 2; bi++) {
                    int row = wn * 32 + bi * 16 + fr;
                    ldm_x4(bf[bi], bbase + row * CH_STRIDE + s * 32 + fc);
                }
                #pragma unroll
                for (int mt = 0; mt < 4; mt++)
                    #pragma unroll
                    for (int nt2 = 0; nt2 < 4; nt2++) {
                        int bi = nt2 >> 1, od = nt2 & 1;
                        MMA_F16(acc[mt][nt2],
                                af[mt][0], af[mt][1], af[mt][2], af[mt][3],
                                bf[bi][od], bf[bi][od + 2]);
                    }
            }
        }

        if (kt + 1 < 16) sts((kt + 1) & 1);
        __syncthreads();
    }

    #pragma unroll
    for (int mt = 0; mt < 4; mt++) {
        int m = m0 + wm * 64 + mt * 16 + r;
        #pragma unroll
        for (int nt = 0; nt < 4; nt++) {
            int n = n0g + wn * 32 + nt * 8 + c2;
            float* a = acc[mt][nt];
            float b0 = bias[n], b1 = bias[n + 1];
            *(float2*)(out + (size_t)m * 256 + n)       = make_float2(a[0] + b0, a[1] + b1);
            *(float2*)(out + (size_t)(m + 8) * 256 + n) = make_float2(a[2] + b0, a[3] + b1);
        }
    }
}

// ---------------------------------------------------------------------------
// Spatial linear attention (attend over N=2048). Block = (bt, h), 8 warps.
// fp16 in/out, packed f32x2 accumulation.
// ---------------------------------------------------------------------------
#define SQS 36
__global__ __launch_bounds__(256)
void spatial_attn_kernel(const __half* __restrict__ q, const __half* __restrict__ k,
                         const __half* __restrict__ v, __half* __restrict__ o)
{
    __shared__ float s_part[8][32][SQS];
    __shared__ float s_kvs[32][SQS];
    __shared__ float s_ksp[8][32];
    __shared__ float s_kss[32];

    const int bt = blockIdx.x;
    const int h  = blockIdx.y;
    const int tid = threadIdx.x;
    const int w = tid >> 5, lane = tid & 31;

    const size_t baseBT = (size_t)bt * N_ * D_ + h * HD_;

    const int mg = lane >> 2;
    const int dg = lane & 3;
    uint64_t acc2[4][4] = {};
    float kss[4] = {0.f, 0.f, 0.f, 0.f};

    const int l0w = w * 256;
    #pragma unroll 4
    for (int l = l0w; l < l0w + 256; l++) {
        const __half* rk = k + baseBT + (size_t)l * D_;
        const __half* rv = v + baseBT + (size_t)l * D_;
        uint2 uk = *(const uint2*)(rk + mg * 4);
        uint4 uv = *(const uint4*)(rv + dg * 8);
        float2 k01 = h2f2(uk.x), k23 = h2f2(uk.y);
        float2 v01 = h2f2(uv.x), v23 = h2f2(uv.y);
        float2 v45 = h2f2(uv.z), v67 = h2f2(uv.w);
        uint64_t vp[4] = { pk2(v01.x, v01.y), pk2(v23.x, v23.y),
                           pk2(v45.x, v45.y), pk2(v67.x, v67.y) };
        float kk[4] = {k01.x, k01.y, k23.x, k23.y};
        #pragma unroll
        for (int i = 0; i < 4; i++) {
            kss[i] += kk[i];
            uint64_t kb = bc2(kk[i]);
            #pragma unroll
            for (int j = 0; j < 4; j++)
                FFMA2(acc2[i][j], kb, vp[j]);
        }
    }
    #pragma unroll
    for (int i = 0; i < 4; i++) {
        float2 p0 = upk2(acc2[i][0]), p1 = upk2(acc2[i][1]);
        float2 p2 = upk2(acc2[i][2]), p3 = upk2(acc2[i][3]);
        *(float4*)&s_part[w][mg*4+i][dg*8]     = make_float4(p0.x, p0.y, p1.x, p1.y);
        *(float4*)&s_part[w][mg*4+i][dg*8 + 4] = make_float4(p2.x, p2.y, p3.x, p3.y);
    }
    if (dg == 0) {
        #pragma unroll
        for (int i = 0; i < 4; i++) s_ksp[w][mg*4+i] = kss[i];
    }
    __syncthreads();

    {
        int m = tid >> 3, dd = (tid & 7) * 4;
        float4 s = make_float4(0.f, 0.f, 0.f, 0.f);
        #pragma unroll
        for (int wi = 0; wi < 8; wi++) {
            float4 p = *(const float4*)&s_part[wi][m][dd];
            s.x += p.x; s.y += p.y; s.z += p.z; s.w += p.w;
        }
        *(float4*)&s_kvs[m][dd] = s;
        if (tid < 32) {
            float s2 = 0.f;
            #pragma unroll
            for (int wi = 0; wi < 8; wi++) s2 += s_ksp[wi][tid];
            s_kss[tid] = s2;
        }
    }
    __syncthreads();

    float* qs = &s_part[w][0][0];
    const int lg = lane >> 3;
    const int d4 = (lane & 7) * 4;

    for (int c = 0; c < 8; c++) {
        const int l0 = l0w + c * 32;
        #pragma unroll
        for (int i2 = 0; i2 < 4; i2++) {
            int idx = lane + i2 * 32;          // 0..127
            int rr = idx >> 2, f = idx & 3;
            uint4 u = *(const uint4*)(q + baseBT + (size_t)(l0 + rr) * D_ + f * 8);
            float2 a = h2f2(u.x), b = h2f2(u.y), cc = h2f2(u.z), d = h2f2(u.w);
            *(float4*)(qs + rr * SQS + f * 8)     = make_float4(a.x, a.y, b.x, b.y);
            *(float4*)(qs + rr * SQS + f * 8 + 4) = make_float4(cc.x, cc.y, d.x, d.y);
        }
        __syncwarp();

        // packed: token-pairs p = (i=2p, 2p+1), tokens l = l0 + i*4 + lg
        uint64_t num2[4][4] = {};
        uint64_t den2[4] = {};
        #pragma unroll
        for (int m = 0; m < 32; m++) {
            float km = s_kss[m];
            uint64_t km2 = bc2(km);
            float4 kr = *(const float4*)&s_kvs[m][d4];
            uint64_t krb[4] = { bc2(kr.x), bc2(kr.y), bc2(kr.z), bc2(kr.w) };
            #pragma unroll
            for (int p = 0; p < 4; p++) {
                float q0 = qs[((2*p)     * 4 + lg) * SQS + m];
                float q1 = qs[((2*p + 1) * 4 + lg) * SQS + m];
                uint64_t qp = pk2(q0, q1);
                FFMA2(den2[p], qp, km2);
                #pragma unroll
                for (int d = 0; d < 4; d++)
                    FFMA2(num2[p][d], qp, krb[d]);
            }
        }
        #pragma unroll
        for (int p = 0; p < 4; p++) {
            float2 dd = upk2(den2[p]);
            float2 n0 = upk2(num2[p][0]), n1 = upk2(num2[p][1]);
            float2 n2 = upk2(num2[p][2]), n3 = upk2(num2[p][3]);
            #pragma unroll
            for (int hh = 0; hh < 2; hh++) {
                int i = 2*p + hh;
                int l = l0 + i * 4 + lg;
                float den = hh ? dd.y : dd.x;
                float m0v = hh ? n0.y : n0.x;
                float m1v = hh ? n1.y : n1.x;
                float m2v = hh ? n2.y : n2.x;
                float m3v = hh ? n3.y : n3.x;
                uint2 uvv = *(const uint2*)(v + baseBT + (size_t)l * D_ + d4);
                float2 vx = h2f2(uvv.x), vy = h2f2(uvv.y);
                float ddn = fmaxf(den + (float)N_, 1e-5f);
                float inv = 1.f / ddn;
                float r0 = (m0v + (float)N_ * vx.x) * inv;
                float r1 = (m1v + (float)N_ * vx.y) * inv;
                float r2 = (m2v + (float)N_ * vy.x) * inv;
                float r3 = (m3v + (float)N_ * vy.y) * inv;
                *(uint2*)(o + baseBT + (size_t)l * D_ + d4) =
                    make_uint2(f2h2(r0, r1), f2h2(r2, r3));
            }
        }
        __syncwarp();
    }
}

// ---------------------------------------------------------------------------
// Temporal linear attention (attend over T=24). Block = (b, n), warp = head.
// packed f32x2 accumulation.
// ---------------------------------------------------------------------------
#define TSM_KVS (8*32*SQS)
#define TSM_Q   (8*24*SQS)
#define TSM_BYTES ((TSM_KVS + TSM_Q + 8*32) * 4)
__global__ __launch_bounds__(256)
void temporal_attn_kernel(const __half* __restrict__ q, const __half* __restrict__ k,
                          const __half* __restrict__ v, __half* __restrict__ o)
{
    extern __shared__ float sm[];
    const int bn = blockIdx.x;
    const int b = bn >> 11;
    const int n = bn & 2047;
    const int tid = threadIdx.x;
    const int h = tid >> 5, lane = tid & 31;

    float* kvs_h = sm + h * 32 * SQS;
    float* q_h   = sm + TSM_KVS + h * 24 * SQS;
    float* kss_h = sm + TSM_KVS + TSM_Q + h * 32;

    const size_t base = ((size_t)b * T_ * N_ + n) * D_ + h * HD_;
    const size_t sT = (size_t)N_ * D_;

    const int mg = lane >> 2;
    const int dg = lane & 3;
    uint64_t acc2[4][4] = {};
    float kss[4] = {0.f, 0.f, 0.f, 0.f};

    #pragma unroll
    for (int t = 0; t < T_; t++) {
        const __half* rk = k + base + (size_t)t * sT;
        const __half* rv = v + base + (size_t)t * sT;
        uint2 uk = *(const uint2*)(rk + mg * 4);
        uint4 uv = *(const uint4*)(rv + dg * 8);
        float2 k01 = h2f2(uk.x), k23 = h2f2(uk.y);
        float2 v01 = h2f2(uv.x), v23 = h2f2(uv.y);
        float2 v45 = h2f2(uv.z), v67 = h2f2(uv.w);
        uint64_t vp[4] = { pk2(v01.x, v01.y), pk2(v23.x, v23.y),
                           pk2(v45.x, v45.y), pk2(v67.x, v67.y) };
        float kk[4] = {k01.x, k01.y, k23.x, k23.y};
        #pragma unroll
        for (int i = 0; i < 4; i++) {
            kss[i] += kk[i];
            uint64_t kb = bc2(kk[i]);
            #pragma unroll
            for (int j = 0; j < 4; j++)
                FFMA2(acc2[i][j], kb, vp[j]);
        }
    }
    #pragma unroll
    for (int i = 0; i < 4; i++) {
        float2 p0 = upk2(acc2[i][0]), p1 = upk2(acc2[i][1]);
        float2 p2 = upk2(acc2[i][2]), p3 = upk2(acc2[i][3]);
        *(float4*)(kvs_h + (mg*4+i) * SQS + dg*8)     = make_float4(p0.x, p0.y, p1.x, p1.y);
        *(float4*)(kvs_h + (mg*4+i) * SQS + dg*8 + 4) = make_float4(p2.x, p2.y, p3.x, p3.y);
    }
    if (dg == 0) {
        #pragma unroll
        for (int i = 0; i < 4; i++) kss_h[mg*4+i] = kss[i];
    }
    #pragma unroll
    for (int i = 0; i < 3; i++) {
        int idx = lane + i * 32;               // 0..95
        int t = idx >> 2, f = idx & 3;
        uint4 u = *(const uint4*)(q + base + (size_t)t * sT + f * 8);
        float2 a = h2f2(u.x), bb = h2f2(u.y), cc = h2f2(u.z), d = h2f2(u.w);
        *(float4*)(q_h + t * SQS + f * 8)     = make_float4(a.x, a.y, bb.x, bb.y);
        *(float4*)(q_h + t * SQS + f * 8 + 4) = make_float4(cc.x, cc.y, d.x, d.y);
    }
    __syncwarp();

    const int tg = lane >> 3;
    const int d4 = (lane & 7) * 4;
    uint64_t num2[3][4] = {};
    uint64_t den2[3] = {};
    #pragma unroll
    for (int m = 0; m < 32; m++) {
        float km = kss_h[m];
        uint64_t km2 = bc2(km);
        float4 kr = *(const float4*)(kvs_h + m * SQS + d4);
        uint64_t krb[4] = { bc2(kr.x), bc2(kr.y), bc2(kr.z), bc2(kr.w) };
        #pragma unroll
        for (int p = 0; p < 3; p++) {
            float q0 = q_h[(tg * 6 + 2*p)     * SQS + m];
            float q1 = q_h[(tg * 6 + 2*p + 1) * SQS + m];
            uint64_t qp = pk2(q0, q1);
            FFMA2(den2[p], qp, km2);
            #pragma unroll
            for (int d = 0; d < 4; d++)
                FFMA2(num2[p][d], qp, krb[d]);
        }
    }
    #pragma unroll
    for (int p = 0; p < 3; p++) {
        float2 dd = upk2(den2[p]);
        float2 n0 = upk2(num2[p][0]), n1 = upk2(num2[p][1]);
        float2 n2 = upk2(num2[p][2]), n3 = upk2(num2[p][3]);
        #pragma unroll
        for (int hh = 0; hh < 2; hh++) {
            int t = tg * 6 + 2*p + hh;
            float den = hh ? dd.y : dd.x;
            float m0v = hh ? n0.y : n0.x;
            float m1v = hh ? n1.y : n1.x;
            float m2v = hh ? n2.y : n2.x;
            float m3v = hh ? n3.y : n3.x;
            uint2 uvv = *(const uint2*)(v + base + (size_t)t * sT + d4);
            float2 vx = h2f2(uvv.x), vy = h2f2(uvv.y);
            float ddn = fmaxf(den + (float)T_, 1e-5f);
            float inv = 1.f / ddn;
            float r0 = (m0v + (float)T_ * vx.x) * inv;
            float r1 = (m1v + (float)T_ * vx.y) * inv;
            float r2 = (m2v + (float)T_ * vy.x) * inv;
            float r3 = (m3v + (float)T_ * vy.y) * inv;
            *(uint2*)(o + base + (size_t)t * sT + d4) =
                make_uint2(f2h2(r0, r1), f2h2(r2, r3));
        }
    }
}

// ---------------------------------------------------------------------------
extern "C" void kernel_launch(void* const* d_in, const int* in_sizes, int n_in,
                              void* d_out, int out_size)
{
    const float* x     = (const float*)d_in[0];
    const float* w_qkv = (const float*)d_in[1];
    const float* w_out = (const float*)d_in[2];
    const float* b_out = (const float*)d_in[3];
    float* out = (float*)d_out;

    __half *q, *k, *v, *os, *ot, *wqh, *woh;
    cudaGetSymbolAddress((void**)&q,   g_q);
    cudaGetSymbolAddress((void**)&k,   g_k);
    cudaGetSymbolAddress((void**)&v,   g_v);
    cudaGetSymbolAddress((void**)&os,  g_os);
    cudaGetSymbolAddress((void**)&ot,  g_ot);
    cudaGetSymbolAddress((void**)&wqh, g_wqh);
    cudaGetSymbolAddress((void**)&woh, g_woh);

    cudaFuncSetAttribute(gemm_qkv_kernel,
                         cudaFuncAttributeMaxDynamicSharedMemorySize, G1_SMEM);
    cudaFuncSetAttribute(gemm_out_kernel,
                         cudaFuncAttributeMaxDynamicSharedMemorySize, G2_SMEM);
    cudaFuncSetAttribute(temporal_attn_kernel,
                         cudaFuncAttributeMaxDynamicSharedMemorySize, TSM_BYTES);

    // 0) convert weights to fp16 scratch
    {
        int total = (768 * 256 + 256 * 512) / 2;
        cvt_weights_kernel<<<(total + 255) / 256, 256>>>(w_qkv, w_out, wqh, woh);
    }
    // 1) QKV projection (fp16 mma, A-resident) + fused q/k l2norm
    gemm_qkv_kernel<<<MTOK / 128, 256, G1_SMEM>>>(x, wqh, q, k, v);

    // 2) spatial attention
    {
        dim3 grid(B_ * T_, H_);
        spatial_attn_kernel<<<grid, 256>>>(q, k, v, os);
    }
    // 3) temporal attention
    temporal_attn_kernel<<<B_ * N_, 256, TSM_BYTES>>>(q, k, v, ot);

    // 4) output projection + bias (fp16 mma, dual-A concat)
    {
        dim3 grid(2, MTOK / 128);
        gemm_out_kernel<<<grid, 256, G2_SMEM>>>(os, ot, woh, b_out, out);
    }
}

// round 9
// speedup vs baseline: 1.2156x; 1.2156x over previous
#include <cuda_runtime.h>
#include <cuda_fp16.h>
#include <math.h>
#include <stdint.h>

#define B_  4
#define T_  24
#define N_  2048
#define D_  256
#define H_  8
#define HD_ 32
#define MTOK (B_*T_*N_)           // 196608 tokens
#define ELEMS ((size_t)MTOK * D_) // 50,331,648

// Scratch (device globals; allocation-free per harness rules). All fp16.
__device__ __half g_q [ELEMS];
__device__ __half g_k [ELEMS];
__device__ __half g_v [ELEMS];
__device__ __half g_os[ELEMS];
__device__ __half g_ot[ELEMS];
__device__ __half g_wqh[768*256];
__device__ __half g_woh[256*512];

// ---------------------------------------------------------------------------
// helpers
// ---------------------------------------------------------------------------
__device__ __forceinline__ uint32_t smem_u32(const void* p) {
    uint32_t a;
    asm("{ .reg .u64 t; cvta.to.shared.u64 t, %1; cvt.u32.u64 %0, t; }"
        : "=r"(a) : "l"(p));
    return a;
}
__device__ __forceinline__ uint32_t f2h2(float a, float b) {
    __half2 h = __floats2half2_rn(a, b);
    return *(uint32_t*)&h;
}
__device__ __forceinline__ uint2 f4h(float4 v) {
    return make_uint2(f2h2(v.x, v.y), f2h2(v.z, v.w));
}
__device__ __forceinline__ float2 h2f2(uint32_t h) {
    return __half22float2(*(__half2*)&h);
}
__device__ __forceinline__ __half2 u2h2(uint32_t u) { return *(__half2*)&u; }
__device__ __forceinline__ void ldm_x4(uint32_t* r, uint32_t addr) {
    asm volatile("ldmatrix.sync.aligned.m8n8.x4.shared.b16 {%0,%1,%2,%3}, [%4];"
                 : "=r"(r[0]), "=r"(r[1]), "=r"(r[2]), "=r"(r[3]) : "r"(addr));
}
#define MMA_F16(d, a0, a1, a2, a3, b0, b1)                                    \
    asm volatile("mma.sync.aligned.m16n8k16.row.col.f32.f16.f16.f32 "         \
                 "{%0,%1,%2,%3}, {%4,%5,%6,%7}, {%8,%9}, {%0,%1,%2,%3};"      \
                 : "+f"(d[0]), "+f"(d[1]), "+f"(d[2]), "+f"(d[3])             \
                 : "r"(a0), "r"(a1), "r"(a2), "r"(a3), "r"(b0), "r"(b1))

// Row strides: 80B (chunk tiles) and 528B (resident A). Both ≡16 (mod 128).
#define CH_STRIDE 80
#define CH_BYTES  (128*CH_STRIDE)
#define AR_STRIDE 528
#define AR_BYTES  (128*AR_STRIDE)

// ---------------------------------------------------------------------------
// weight pre-conversion: f32 -> f16 (once per launch)
// ---------------------------------------------------------------------------
__global__ void cvt_weights_kernel(const float* __restrict__ wq,
                                   const float* __restrict__ wo,
                                   __half* __restrict__ wqh,
                                   __half* __restrict__ woh)
{
    int i = blockIdx.x * blockDim.x + threadIdx.x;
    const int NQ = 768 * 256 / 2;
    const int NO = 256 * 512 / 2;
    if (i < NQ) {
        float2 f = *(const float2*)(wq + i * 2);
        *(uint32_t*)(wqh + i * 2) = f2h2(f.x, f.y);
    } else if (i < NQ + NO) {
        int j = i - NQ;
        float2 f = *(const float2*)(wo + j * 2);
        *(uint32_t*)(woh + j * 2) = f2h2(f.x, f.y);
    }
}

// ===========================================================================
// GEMM1 (A-resident, fp16): qkv[M,768] = x[M,256] * w_qkv[768,256]^T
// ===========================================================================
#define G1_SMEM (AR_BYTES + 2*CH_BYTES)   // 88064

__global__ __launch_bounds__(256, 2)
void gemm_qkv_kernel(const float* __restrict__ A, const __half* __restrict__ Bw,
                     __half* __restrict__ outq, __half* __restrict__ outk,
                     __half* __restrict__ outv)
{
    extern __shared__ __align__(16) char smem[];
    const uint32_t sbase = smem_u32(smem);
    const int tid  = threadIdx.x;
    const int lane = tid & 31;
    const int wid  = tid >> 5;
    const int wm   = wid & 1;
    const int wn   = wid >> 1;
    const int m0   = blockIdx.x * 128;

    const int ar = tid >> 1;
    const int ac = tid & 1;
    const int fr = lane & 15;
    const int fc = (lane >> 4) * 16;
    const int r  = lane >> 2;
    const int c2 = (lane & 3) << 1;

    #pragma unroll
    for (int j = 0; j < 8; j++) {
        const float* ap = A + (size_t)(m0 + ar) * 256 + (ac * 8 + j) * 16;
        uint2 h0 = f4h(*(const float4*)(ap + 0));
        uint2 h1 = f4h(*(const float4*)(ap + 4));
        uint2 h2 = f4h(*(const float4*)(ap + 8));
        uint2 h3 = f4h(*(const float4*)(ap + 12));
        char* dst = smem + ar * AR_STRIDE + (ac * 8 + j) * 32;
        *(uint4*)(dst)      = make_uint4(h0.x, h0.y, h1.x, h1.y);
        *(uint4*)(dst + 16) = make_uint4(h2.x, h2.y, h3.x, h3.y);
    }

    uint4 hb0, hb1;
    auto ldgB = [&](int it) {
        const int nt = it >> 3, kt = it & 7;
        const __half* bp = Bw + (size_t)(nt * 128 + ar) * 256 + kt * 32 + ac * 16;
        hb0 = *(const uint4*)(bp);
        hb1 = *(const uint4*)(bp + 8);
    };
    auto stsB = [&](int buf) {
        char* dst = smem + AR_BYTES + buf * CH_BYTES + ar * CH_STRIDE + ac * 32;
        *(uint4*)(dst)      = hb0;
        *(uint4*)(dst + 16) = hb1;
    };

    float acc[4][4][4];
    #pragma unroll
    for (int i = 0; i < 4; i++)
        #pragma unroll
        for (int j = 0; j < 4; j++)
            #pragma unroll
            for (int c = 0; c < 4; c++) acc[i][j][c] = 0.f;

    ldgB(0);
    stsB(0);
    __syncthreads();

    #pragma unroll 1
    for (int it = 0; it < 48; it++) {
        if (it + 1 < 48) ldgB(it + 1);

        {
            const int kt = it & 7;
            const uint32_t abase = sbase + kt * 64;
            const uint32_t bbase = sbase + AR_BYTES + (it & 1) * CH_BYTES;
            #pragma unroll
            for (int s = 0; s < 2; s++) {
                uint32_t af[4][4], bf[2][4];
                #pragma unroll
                for (int mt = 0; mt < 4; mt++) {
                    int row = wm * 64 + mt * 16 + fr;
                    ldm_x4(af[mt], abase + row * AR_STRIDE + s * 32 + fc);
                }
                #pragma unroll
                for (int bi = 0; bi < 2; bi++) {
                    int row = wn * 32 + bi * 16 + fr;
                    ldm_x4(bf[bi], bbase + row * CH_STRIDE + s * 32 + fc);
                }
                #pragma unroll
                for (int mt = 0; mt < 4; mt++)
                    #pragma unroll
                    for (int nt2 = 0; nt2 < 4; nt2++) {
                        int bi = nt2 >> 1, od = nt2 & 1;
                        MMA_F16(acc[mt][nt2],
                                af[mt][0], af[mt][1], af[mt][2], af[mt][3],
                                bf[bi][od], bf[bi][od + 2]);
                    }
            }
        }

        if ((it & 7) == 7) {
            const int n0g = (it >> 3) * 128;
            const int sel = n0g >> 8;

            if (sel < 2) {
                #pragma unroll
                for (int mt = 0; mt < 4; mt++) {
                    float sslo = 0.f, sshi = 0.f;
                    #pragma unroll
                    for (int nt2 = 0; nt2 < 4; nt2++) {
                        sslo = fmaf(acc[mt][nt2][0], acc[mt][nt2][0], sslo);
                        sslo = fmaf(acc[mt][nt2][1], acc[mt][nt2][1], sslo);
                        sshi = fmaf(acc[mt][nt2][2], acc[mt][nt2][2], sshi);
                        sshi = fmaf(acc[mt][nt2][3], acc[mt][nt2][3], sshi);
                    }
                    sslo += __shfl_xor_sync(0xffffffffu, sslo, 1);
                    sslo += __shfl_xor_sync(0xffffffffu, sslo, 2);
                    sshi += __shfl_xor_sync(0xffffffffu, sshi, 1);
                    sshi += __shfl_xor_sync(0xffffffffu, sshi, 2);
                    float slo = 1.f / fmaxf(sqrtf(sslo), 1e-12f);
                    float shi = 1.f / fmaxf(sqrtf(sshi), 1e-12f);
                    #pragma unroll
                    for (int nt2 = 0; nt2 < 4; nt2++) {
                        acc[mt][nt2][0] *= slo; acc[mt][nt2][1] *= slo;
                        acc[mt][nt2][2] *= shi; acc[mt][nt2][3] *= shi;
                    }
                }
            }

            __half* dst = (sel == 0) ? outq : ((sel == 1) ? outk : outv);
            #pragma unroll
            for (int mt = 0; mt < 4; mt++) {
                int m = m0 + wm * 64 + mt * 16 + r;
                #pragma unroll
                for (int nt2 = 0; nt2 < 4; nt2++) {
                    int col = ((n0g + wn * 32 + nt2 * 8 + c2) & 255);
                    float* a = acc[mt][nt2];
                    *(uint32_t*)(dst + (size_t)m * 256 + col)       = f2h2(a[0], a[1]);
                    *(uint32_t*)(dst + (size_t)(m + 8) * 256 + col) = f2h2(a[2], a[3]);
                    a[0] = a[1] = a[2] = a[3] = 0.f;
                }
            }
        }

        if (it + 1 < 48) stsB((it + 1) & 1);
        __syncthreads();
    }
}

// ===========================================================================
// GEMM2 (fp16 in / f32 out): out = [os|ot] * w_out^T + b
// ===========================================================================
#define G2_SMEM (4*CH_BYTES)   // 40960

__global__ __launch_bounds__(256, 2)
void gemm_out_kernel(const __half* __restrict__ A0, const __half* __restrict__ A1,
                     const __half* __restrict__ Bw,
                     const float* __restrict__ bias,
                     float* __restrict__ out)
{
    extern __shared__ __align__(16) char smem[];
    const uint32_t sbase = smem_u32(smem);
    const int tid  = threadIdx.x;
    const int lane = tid & 31;
    const int wid  = tid >> 5;
    const int wm   = wid & 1;
    const int wn   = wid >> 1;
    const int m0   = blockIdx.y * 128;
    const int n0g  = blockIdx.x * 128;

    const int ar = tid >> 1;
    const int ac = tid & 1;
    const int fr = lane & 15;
    const int fc = (lane >> 4) * 16;
    const int r  = lane >> 2;
    const int c2 = (lane & 3) << 1;

    uint4 ua0, ua1, ub0, ub1;
    auto ldg = [&](int kt) {
        const int k0 = kt * 32;
        const __half* Asrc = (k0 < 256) ? A0 : A1;
        const int kc = k0 & 255;
        const __half* ap = Asrc + (size_t)(m0 + ar) * 256 + kc + ac * 16;
        ua0 = *(const uint4*)(ap);
        ua1 = *(const uint4*)(ap + 8);
        const __half* bp = Bw + (size_t)(n0g + ar) * 512 + k0 + ac * 16;
        ub0 = *(const uint4*)(bp);
        ub1 = *(const uint4*)(bp + 8);
    };
    auto sts = [&](int buf) {
        char* da = smem + buf * 2 * CH_BYTES + ar * CH_STRIDE + ac * 32;
        *(uint4*)(da)      = ua0;
        *(uint4*)(da + 16) = ua1;
        char* db = da + CH_BYTES;
        *(uint4*)(db)      = ub0;
        *(uint4*)(db + 16) = ub1;
    };

    float acc[4][4][4];
    #pragma unroll
    for (int i = 0; i < 4; i++)
        #pragma unroll
        for (int j = 0; j < 4; j++)
            #pragma unroll
            for (int c = 0; c < 4; c++) acc[i][j][c] = 0.f;

    ldg(0);
    sts(0);
    __syncthreads();

    #pragma unroll 1
    for (int kt = 0; kt < 16; kt++) {
        if (kt + 1 < 16) ldg(kt + 1);

        {
            const uint32_t abase = sbase + (kt & 1) * 2 * CH_BYTES;
            const uint32_t bbase = abase + CH_BYTES;
            #pragma unroll
            for (int s = 0; s < 2; s++) {
                uint32_t af[4][4], bf[2][4];
                #pragma unroll
                for (int mt = 0; mt < 4; mt++) {
                    int row = wm * 64 + mt * 16 + fr;
                    ldm_x4(af[mt], abase + row * CH_STRIDE + s * 32 + fc);
                }
                #pragma unroll
                for (int bi = 0; bi < 2; bi++) {
                    int row = wn * 32 + bi * 16 + fr;
                    ldm_x4(bf[bi], bbase + row * CH_STRIDE + s * 32 + fc);
                }
                #pragma unroll
                for (int mt = 0; mt < 4; mt++)
                    #pragma unroll
                    for (int nt2 = 0; nt2 < 4; nt2++) {
                        int bi = nt2 >> 1, od = nt2 & 1;
                        MMA_F16(acc[mt][nt2],
                                af[mt][0], af[mt][1], af[mt][2], af[mt][3],
                                bf[bi][od], bf[bi][od + 2]);
                    }
            }
        }

        if (kt + 1 < 16) sts((kt + 1) & 1);
        __syncthreads();
    }

    #pragma unroll
    for (int mt = 0; mt < 4; mt++) {
        int m = m0 + wm * 64 + mt * 16 + r;
        #pragma unroll
        for (int nt = 0; nt < 4; nt++) {
            int n = n0g + wn * 32 + nt * 8 + c2;
            float* a = acc[mt][nt];
            float b0 = bias[n], b1 = bias[n + 1];
            *(float2*)(out + (size_t)m * 256 + n)       = make_float2(a[0] + b0, a[1] + b1);
            *(float2*)(out + (size_t)(m + 8) * 256 + n) = make_float2(a[2] + b0, a[3] + b1);
        }
    }
}

// ---------------------------------------------------------------------------
// Spatial linear attention (attend over N=2048). Block = (bt, h), 8 warps.
// Phase 1: native half2 HFMA2 accumulation (no cvt, no packs).
// Phase 2: f32 (round-7 known-good).
// ---------------------------------------------------------------------------
#define SQS 36
__global__ __launch_bounds__(256)
void spatial_attn_kernel(const __half* __restrict__ q, const __half* __restrict__ k,
                         const __half* __restrict__ v, __half* __restrict__ o)
{
    __shared__ float s_part[8][32][SQS];
    __shared__ float s_kvs[32][SQS];
    __shared__ float s_ksp[8][32];
    __shared__ float s_kss[32];

    const int bt = blockIdx.x;
    const int h  = blockIdx.y;
    const int tid = threadIdx.x;
    const int w = tid >> 5, lane = tid & 31;

    const size_t baseBT = (size_t)bt * N_ * D_ + h * HD_;

    const int mg = lane >> 2;
    const int dg = lane & 3;

    const __half2 hz = __float2half2_rn(0.f);
    __half2 acc2[4][4];
    #pragma unroll
    for (int i = 0; i < 4; i++)
        #pragma unroll
        for (int j = 0; j < 4; j++) acc2[i][j] = hz;
    __half2 kss01 = hz, kss23 = hz;

    const int l0w = w * 256;
    #pragma unroll 4
    for (int l = l0w; l < l0w + 256; l++) {
        const __half* rk = k + baseBT + (size_t)l * D_;
        const __half* rv = v + baseBT + (size_t)l * D_;
        uint2 uk = *(const uint2*)(rk + mg * 4);
        uint4 uv = *(const uint4*)(rv + dg * 8);
        __half2 k01 = u2h2(uk.x), k23 = u2h2(uk.y);
        kss01 = __hadd2(kss01, k01);
        kss23 = __hadd2(kss23, k23);
        __half2 vj[4] = { u2h2(uv.x), u2h2(uv.y), u2h2(uv.z), u2h2(uv.w) };
        __half2 kb[4] = { __low2half2(k01), __high2half2(k01),
                          __low2half2(k23), __high2half2(k23) };
        #pragma unroll
        for (int i = 0; i < 4; i++)
            #pragma unroll
            for (int j = 0; j < 4; j++)
                acc2[i][j] = __hfma2(kb[i], vj[j], acc2[i][j]);
    }
    #pragma unroll
    for (int i = 0; i < 4; i++) {
        float2 p0 = __half22float2(acc2[i][0]);
        float2 p1 = __half22float2(acc2[i][1]);
        float2 p2 = __half22float2(acc2[i][2]);
        float2 p3 = __half22float2(acc2[i][3]);
        *(float4*)&s_part[w][mg*4+i][dg*8]     = make_float4(p0.x, p0.y, p1.x, p1.y);
        *(float4*)&s_part[w][mg*4+i][dg*8 + 4] = make_float4(p2.x, p2.y, p3.x, p3.y);
    }
    if (dg == 0) {
        float2 a = __half22float2(kss01);
        float2 b = __half22float2(kss23);
        s_ksp[w][mg*4+0] = a.x; s_ksp[w][mg*4+1] = a.y;
        s_ksp[w][mg*4+2] = b.x; s_ksp[w][mg*4+3] = b.y;
    }
    __syncthreads();

    {
        int m = tid >> 3, dd = (tid & 7) * 4;
        float4 s = make_float4(0.f, 0.f, 0.f, 0.f);
        #pragma unroll
        for (int wi = 0; wi < 8; wi++) {
            float4 p = *(const float4*)&s_part[wi][m][dd];
            s.x += p.x; s.y += p.y; s.z += p.z; s.w += p.w;
        }
        *(float4*)&s_kvs[m][dd] = s;
        if (tid < 32) {
            float s2 = 0.f;
            #pragma unroll
            for (int wi = 0; wi < 8; wi++) s2 += s_ksp[wi][tid];
            s_kss[tid] = s2;
        }
    }
    __syncthreads();

    float* qs = &s_part[w][0][0];
    const int lg = lane >> 3;
    const int d4 = (lane & 7) * 4;

    for (int c = 0; c < 8; c++) {
        const int l0 = l0w + c * 32;
        #pragma unroll
        for (int i2 = 0; i2 < 4; i2++) {
            int idx = lane + i2 * 32;          // 0..127
            int rr = idx >> 2, f = idx & 3;
            uint4 u = *(const uint4*)(q + baseBT + (size_t)(l0 + rr) * D_ + f * 8);
            float2 a = h2f2(u.x), b = h2f2(u.y), cc = h2f2(u.z), d = h2f2(u.w);
            *(float4*)(qs + rr * SQS + f * 8)     = make_float4(a.x, a.y, b.x, b.y);
            *(float4*)(qs + rr * SQS + f * 8 + 4) = make_float4(cc.x, cc.y, d.x, d.y);
        }
        __syncwarp();

        float num[8][4] = {};
        float den[8] = {};
        #pragma unroll
        for (int m = 0; m < 32; m++) {
            float km = s_kss[m];
            float4 kr = *(const float4*)&s_kvs[m][d4];
            #pragma unroll
            for (int i = 0; i < 8; i++) {
                float qm = qs[(i * 4 + lg) * SQS + m];
                den[i] = fmaf(qm, km, den[i]);
                num[i][0] = fmaf(qm, kr.x, num[i][0]);
                num[i][1] = fmaf(qm, kr.y, num[i][1]);
                num[i][2] = fmaf(qm, kr.z, num[i][2]);
                num[i][3] = fmaf(qm, kr.w, num[i][3]);
            }
        }
        #pragma unroll
        for (int i = 0; i < 8; i++) {
            int l = l0 + i * 4 + lg;
            uint2 uvv = *(const uint2*)(v + baseBT + (size_t)l * D_ + d4);
            float2 vx = h2f2(uvv.x), vy = h2f2(uvv.y);
            float ddn = fmaxf(den[i] + (float)N_, 1e-5f);
            float inv = 1.f / ddn;
            float r0 = (num[i][0] + (float)N_ * vx.x) * inv;
            float r1 = (num[i][1] + (float)N_ * vx.y) * inv;
            float r2 = (num[i][2] + (float)N_ * vy.x) * inv;
            float r3 = (num[i][3] + (float)N_ * vy.y) * inv;
            *(uint2*)(o + baseBT + (size_t)l * D_ + d4) =
                make_uint2(f2h2(r0, r1), f2h2(r2, r3));
        }
        __syncwarp();
    }
}

// ---------------------------------------------------------------------------
// Temporal linear attention (attend over T=24). Block = (b, n), warp = head.
// Phase 1 half2; phase 2 f32 (round-7).
// ---------------------------------------------------------------------------
#define TSM_KVS (8*32*SQS)
#define TSM_Q   (8*24*SQS)
#define TSM_BYTES ((TSM_KVS + TSM_Q + 8*32) * 4)
__global__ __launch_bounds__(256)
void temporal_attn_kernel(const __half* __restrict__ q, const __half* __restrict__ k,
                          const __half* __restrict__ v, __half* __restrict__ o)
{
    extern __shared__ float sm[];
    const int bn = blockIdx.x;
    const int b = bn >> 11;
    const int n = bn & 2047;
    const int tid = threadIdx.x;
    const int h = tid >> 5, lane = tid & 31;

    float* kvs_h = sm + h * 32 * SQS;
    float* q_h   = sm + TSM_KVS + h * 24 * SQS;
    float* kss_h = sm + TSM_KVS + TSM_Q + h * 32;

    const size_t base = ((size_t)b * T_ * N_ + n) * D_ + h * HD_;
    const size_t sT = (size_t)N_ * D_;

    const int mg = lane >> 2;
    const int dg = lane & 3;

    const __half2 hz = __float2half2_rn(0.f);
    __half2 acc2[4][4];
    #pragma unroll
    for (int i = 0; i < 4; i++)
        #pragma unroll
        for (int j = 0; j < 4; j++) acc2[i][j] = hz;
    __half2 kss01 = hz, kss23 = hz;

    #pragma unroll
    for (int t = 0; t < T_; t++) {
        const __half* rk = k + base + (size_t)t * sT;
        const __half* rv = v + base + (size_t)t * sT;
        uint2 uk = *(const uint2*)(rk + mg * 4);
        uint4 uv = *(const uint4*)(rv + dg * 8);
        __half2 k01 = u2h2(uk.x), k23 = u2h2(uk.y);
        kss01 = __hadd2(kss01, k01);
        kss23 = __hadd2(kss23, k23);
        __half2 vj[4] = { u2h2(uv.x), u2h2(uv.y), u2h2(uv.z), u2h2(uv.w) };
        __half2 kb[4] = { __low2half2(k01), __high2half2(k01),
                          __low2half2(k23), __high2half2(k23) };
        #pragma unroll
        for (int i = 0; i < 4; i++)
            #pragma unroll
            for (int j = 0; j < 4; j++)
                acc2[i][j] = __hfma2(kb[i], vj[j], acc2[i][j]);
    }
    #pragma unroll
    for (int i = 0; i < 4; i++) {
        float2 p0 = __half22float2(acc2[i][0]);
        float2 p1 = __half22float2(acc2[i][1]);
        float2 p2 = __half22float2(acc2[i][2]);
        float2 p3 = __half22float2(acc2[i][3]);
        *(float4*)(kvs_h + (mg*4+i) * SQS + dg*8)     = make_float4(p0.x, p0.y, p1.x, p1.y);
        *(float4*)(kvs_h + (mg*4+i) * SQS + dg*8 + 4) = make_float4(p2.x, p2.y, p3.x, p3.y);
    }
    if (dg == 0) {
        float2 a = __half22float2(kss01);
        float2 b = __half22float2(kss23);
        kss_h[mg*4+0] = a.x; kss_h[mg*4+1] = a.y;
        kss_h[mg*4+2] = b.x; kss_h[mg*4+3] = b.y;
    }
    #pragma unroll
    for (int i = 0; i < 3; i++) {
        int idx = lane + i * 32;               // 0..95
        int t = idx >> 2, f = idx & 3;
        uint4 u = *(const uint4*)(q + base + (size_t)t * sT + f * 8);
        float2 a = h2f2(u.x), bb = h2f2(u.y), cc = h2f2(u.z), d = h2f2(u.w);
        *(float4*)(q_h + t * SQS + f * 8)     = make_float4(a.x, a.y, bb.x, bb.y);
        *(float4*)(q_h + t * SQS + f * 8 + 4) = make_float4(cc.x, cc.y, d.x, d.y);
    }
    __syncwarp();

    const int tg = lane >> 3;
    const int d4 = (lane & 7) * 4;
    float num[6][4] = {};
    float den[6] = {};
    #pragma unroll
    for (int m = 0; m < 32; m++) {
        float km = kss_h[m];
        float4 kr = *(const float4*)(kvs_h + m * SQS + d4);
        #pragma unroll
        for (int i = 0; i < 6; i++) {
            float qm = q_h[(tg * 6 + i) * SQS + m];
            den[i] = fmaf(qm, km, den[i]);
            num[i][0] = fmaf(qm, kr.x, num[i][0]);
            num[i][1] = fmaf(qm, kr.y, num[i][1]);
            num[i][2] = fmaf(qm, kr.z, num[i][2]);
            num[i][3] = fmaf(qm, kr.w, num[i][3]);
        }
    }
    #pragma unroll
    for (int i = 0; i < 6; i++) {
        int t = tg * 6 + i;
        uint2 uvv = *(const uint2*)(v + base + (size_t)t * sT + d4);
        float2 vx = h2f2(uvv.x), vy = h2f2(uvv.y);
        float ddn = fmaxf(den[i] + (float)T_, 1e-5f);
        float inv = 1.f / ddn;
        float r0 = (num[i][0] + (float)T_ * vx.x) * inv;
        float r1 = (num[i][1] + (float)T_ * vx.y) * inv;
        float r2 = (num[i][2] + (float)T_ * vy.x) * inv;
        float r3 = (num[i][3] + (float)T_ * vy.y) * inv;
        *(uint2*)(o + base + (size_t)t * sT + d4) =
            make_uint2(f2h2(r0, r1), f2h2(r2, r3));
    }
}

// ---------------------------------------------------------------------------
extern "C" void kernel_launch(void* const* d_in, const int* in_sizes, int n_in,
                              void* d_out, int out_size)
{
    const float* x     = (const float*)d_in[0];
    const float* w_qkv = (const float*)d_in[1];
    const float* w_out = (const float*)d_in[2];
    const float* b_out = (const float*)d_in[3];
    float* out = (float*)d_out;

    __half *q, *k, *v, *os, *ot, *wqh, *woh;
    cudaGetSymbolAddress((void**)&q,   g_q);
    cudaGetSymbolAddress((void**)&k,   g_k);
    cudaGetSymbolAddress((void**)&v,   g_v);
    cudaGetSymbolAddress((void**)&os,  g_os);
    cudaGetSymbolAddress((void**)&ot,  g_ot);
    cudaGetSymbolAddress((void**)&wqh, g_wqh);
    cudaGetSymbolAddress((void**)&woh, g_woh);

    cudaFuncSetAttribute(gemm_qkv_kernel,
                         cudaFuncAttributeMaxDynamicSharedMemorySize, G1_SMEM);
    cudaFuncSetAttribute(gemm_out_kernel,
                         cudaFuncAttributeMaxDynamicSharedMemorySize, G2_SMEM);
    cudaFuncSetAttribute(temporal_attn_kernel,
                         cudaFuncAttributeMaxDynamicSharedMemorySize, TSM_BYTES);

    // 0) convert weights to fp16 scratch
    {
        int total = (768 * 256 + 256 * 512) / 2;
        cvt_weights_kernel<<<(total + 255) / 256, 256>>>(w_qkv, w_out, wqh, woh);
    }
    // 1) QKV projection (fp16 mma, A-resident) + fused q/k l2norm
    gemm_qkv_kernel<<<MTOK / 128, 256, G1_SMEM>>>(x, wqh, q, k, v);

    // 2) spatial attention
    {
        dim3 grid(B_ * T_, H_);
        spatial_attn_kernel<<<grid, 256>>>(q, k, v, os);
    }
    // 3) temporal attention
    temporal_attn_kernel<<<B_ * N_, 256, TSM_BYTES>>>(q, k, v, ot);

    // 4) output projection + bias (fp16 mma, dual-A concat)
    {
        dim3 grid(2, MTOK / 128);
        gemm_out_kernel<<<grid, 256, G2_SMEM>>>(os, ot, woh, b_out, out);
    }
}

// round 10
// speedup vs baseline: 1.3281x; 1.0926x over previous
#include <cuda_runtime.h>
#include <cuda_fp16.h>
#include <math.h>
#include <stdint.h>

#define B_  4
#define T_  24
#define N_  2048
#define D_  256
#define H_  8
#define HD_ 32
#define MTOK (B_*T_*N_)           // 196608 tokens
#define ELEMS ((size_t)MTOK * D_) // 50,331,648

// Scratch (device globals; allocation-free per harness rules). All fp16.
__device__ __half g_q [ELEMS];
__device__ __half g_k [ELEMS];
__device__ __half g_v [ELEMS];
__device__ __half g_os[ELEMS];
__device__ __half g_ot[ELEMS];
__device__ __half g_wqh[768*256];
__device__ __half g_woh[256*512];

// ---------------------------------------------------------------------------
// helpers
// ---------------------------------------------------------------------------
__device__ __forceinline__ uint32_t smem_u32(const void* p) {
    uint32_t a;
    asm("{ .reg .u64 t; cvta.to.shared.u64 t, %1; cvt.u32.u64 %0, t; }"
        : "=r"(a) : "l"(p));
    return a;
}
__device__ __forceinline__ uint32_t f2h2(float a, float b) {
    __half2 h = __floats2half2_rn(a, b);
    return *(uint32_t*)&h;
}
__device__ __forceinline__ uint2 f4h(float4 v) {
    return make_uint2(f2h2(v.x, v.y), f2h2(v.z, v.w));
}
__device__ __forceinline__ float2 h2f2(uint32_t h) {
    return __half22float2(*(__half2*)&h);
}
__device__ __forceinline__ __half2 u2h2(uint32_t u) { return *(__half2*)&u; }
__device__ __forceinline__ void ldm_x4(uint32_t* r, uint32_t addr) {
    asm volatile("ldmatrix.sync.aligned.m8n8.x4.shared.b16 {%0,%1,%2,%3}, [%4];"
                 : "=r"(r[0]), "=r"(r[1]), "=r"(r[2]), "=r"(r[3]) : "r"(addr));
}
#define MMA_F16(d, a0, a1, a2, a3, b0, b1)                                    \
    asm volatile("mma.sync.aligned.m16n8k16.row.col.f32.f16.f16.f32 "         \
                 "{%0,%1,%2,%3}, {%4,%5,%6,%7}, {%8,%9}, {%0,%1,%2,%3};"      \
                 : "+f"(d[0]), "+f"(d[1]), "+f"(d[2]), "+f"(d[3])             \
                 : "r"(a0), "r"(a1), "r"(a2), "r"(a3), "r"(b0), "r"(b1))

// Row strides: 80B (chunk tiles) and 528B (resident A). Both ≡16 (mod 128).
#define CH_STRIDE 80
#define CH_BYTES  (128*CH_STRIDE)
#define AR_STRIDE 528
#define AR_BYTES  (128*AR_STRIDE)

// ---------------------------------------------------------------------------
// weight pre-conversion: f32 -> f16 (once per launch)
// ---------------------------------------------------------------------------
__global__ void cvt_weights_kernel(const float* __restrict__ wq,
                                   const float* __restrict__ wo,
                                   __half* __restrict__ wqh,
                                   __half* __restrict__ woh)
{
    int i = blockIdx.x * blockDim.x + threadIdx.x;
    const int NQ = 768 * 256 / 2;
    const int NO = 256 * 512 / 2;
    if (i < NQ) {
        float2 f = *(const float2*)(wq + i * 2);
        *(uint32_t*)(wqh + i * 2) = f2h2(f.x, f.y);
    } else if (i < NQ + NO) {
        int j = i - NQ;
        float2 f = *(const float2*)(wo + j * 2);
        *(uint32_t*)(woh + j * 2) = f2h2(f.x, f.y);
    }
}

// ===========================================================================
// GEMM1 (A-resident, fp16): qkv[M,768] = x[M,256] * w_qkv[768,256]^T
// ===========================================================================
#define G1_SMEM (AR_BYTES + 2*CH_BYTES)   // 88064

__global__ __launch_bounds__(256, 2)
void gemm_qkv_kernel(const float* __restrict__ A, const __half* __restrict__ Bw,
                     __half* __restrict__ outq, __half* __restrict__ outk,
                     __half* __restrict__ outv)
{
    extern __shared__ __align__(16) char smem[];
    const uint32_t sbase = smem_u32(smem);
    const int tid  = threadIdx.x;
    const int lane = tid & 31;
    const int wid  = tid >> 5;
    const int wm   = wid & 1;
    const int wn   = wid >> 1;
    const int m0   = blockIdx.x * 128;

    const int ar = tid >> 1;
    const int ac = tid & 1;
    const int fr = lane & 15;
    const int fc = (lane >> 4) * 16;
    const int r  = lane >> 2;
    const int c2 = (lane & 3) << 1;

    #pragma unroll
    for (int j = 0; j < 8; j++) {
        const float* ap = A + (size_t)(m0 + ar) * 256 + (ac * 8 + j) * 16;
        uint2 h0 = f4h(*(const float4*)(ap + 0));
        uint2 h1 = f4h(*(const float4*)(ap + 4));
        uint2 h2 = f4h(*(const float4*)(ap + 8));
        uint2 h3 = f4h(*(const float4*)(ap + 12));
        char* dst = smem + ar * AR_STRIDE + (ac * 8 + j) * 32;
        *(uint4*)(dst)      = make_uint4(h0.x, h0.y, h1.x, h1.y);
        *(uint4*)(dst + 16) = make_uint4(h2.x, h2.y, h3.x, h3.y);
    }

    uint4 hb0, hb1;
    auto ldgB = [&](int it) {
        const int nt = it >> 3, kt = it & 7;
        const __half* bp = Bw + (size_t)(nt * 128 + ar) * 256 + kt * 32 + ac * 16;
        hb0 = *(const uint4*)(bp);
        hb1 = *(const uint4*)(bp + 8);
    };
    auto stsB = [&](int buf) {
        char* dst = smem + AR_BYTES + buf * CH_BYTES + ar * CH_STRIDE + ac * 32;
        *(uint4*)(dst)      = hb0;
        *(uint4*)(dst + 16) = hb1;
    };

    float acc[4][4][4];
    #pragma unroll
    for (int i = 0; i < 4; i++)
        #pragma unroll
        for (int j = 0; j < 4; j++)
            #pragma unroll
            for (int c = 0; c < 4; c++) acc[i][j][c] = 0.f;

    ldgB(0);
    stsB(0);
    __syncthreads();

    #pragma unroll 1
    for (int it = 0; it < 48; it++) {
        if (it + 1 < 48) ldgB(it + 1);

        {
            const int kt = it & 7;
            const uint32_t abase = sbase + kt * 64;
            const uint32_t bbase = sbase + AR_BYTES + (it & 1) * CH_BYTES;
            #pragma unroll
            for (int s = 0; s < 2; s++) {
                uint32_t af[4][4], bf[2][4];
                #pragma unroll
                for (int mt = 0; mt < 4; mt++) {
                    int row = wm * 64 + mt * 16 + fr;
                    ldm_x4(af[mt], abase + row * AR_STRIDE + s * 32 + fc);
                }
                #pragma unroll
                for (int bi = 0; bi < 2; bi++) {
                    int row = wn * 32 + bi * 16 + fr;
                    ldm_x4(bf[bi], bbase + row * CH_STRIDE + s * 32 + fc);
                }
                #pragma unroll
                for (int mt = 0; mt < 4; mt++)
                    #pragma unroll
                    for (int nt2 = 0; nt2 < 4; nt2++) {
                        int bi = nt2 >> 1, od = nt2 & 1;
                        MMA_F16(acc[mt][nt2],
                                af[mt][0], af[mt][1], af[mt][2], af[mt][3],
                                bf[bi][od], bf[bi][od + 2]);
                    }
            }
        }

        if ((it & 7) == 7) {
            const int n0g = (it >> 3) * 128;
            const int sel = n0g >> 8;

            if (sel < 2) {
                #pragma unroll
                for (int mt = 0; mt < 4; mt++) {
                    float sslo = 0.f, sshi = 0.f;
                    #pragma unroll
                    for (int nt2 = 0; nt2 < 4; nt2++) {
                        sslo = fmaf(acc[mt][nt2][0], acc[mt][nt2][0], sslo);
                        sslo = fmaf(acc[mt][nt2][1], acc[mt][nt2][1], sslo);
                        sshi = fmaf(acc[mt][nt2][2], acc[mt][nt2][2], sshi);
                        sshi = fmaf(acc[mt][nt2][3], acc[mt][nt2][3], sshi);
                    }
                    sslo += __shfl_xor_sync(0xffffffffu, sslo, 1);
                    sslo += __shfl_xor_sync(0xffffffffu, sslo, 2);
                    sshi += __shfl_xor_sync(0xffffffffu, sshi, 1);
                    sshi += __shfl_xor_sync(0xffffffffu, sshi, 2);
                    float slo = 1.f / fmaxf(sqrtf(sslo), 1e-12f);
                    float shi = 1.f / fmaxf(sqrtf(sshi), 1e-12f);
                    #pragma unroll
                    for (int nt2 = 0; nt2 < 4; nt2++) {
                        acc[mt][nt2][0] *= slo; acc[mt][nt2][1] *= slo;
                        acc[mt][nt2][2] *= shi; acc[mt][nt2][3] *= shi;
                    }
                }
            }

            __half* dst = (sel == 0) ? outq : ((sel == 1) ? outk : outv);
            #pragma unroll
            for (int mt = 0; mt < 4; mt++) {
                int m = m0 + wm * 64 + mt * 16 + r;
                #pragma unroll
                for (int nt2 = 0; nt2 < 4; nt2++) {
                    int col = ((n0g + wn * 32 + nt2 * 8 + c2) & 255);
                    float* a = acc[mt][nt2];
                    *(uint32_t*)(dst + (size_t)m * 256 + col)       = f2h2(a[0], a[1]);
                    *(uint32_t*)(dst + (size_t)(m + 8) * 256 + col) = f2h2(a[2], a[3]);
                    a[0] = a[1] = a[2] = a[3] = 0.f;
                }
            }
        }

        if (it + 1 < 48) stsB((it + 1) & 1);
        __syncthreads();
    }
}

// ===========================================================================
// GEMM2 (fp16 in / f32 out): out = [os|ot] * w_out^T + b
// ===========================================================================
#define G2_SMEM (4*CH_BYTES)   // 40960

__global__ __launch_bounds__(256, 2)
void gemm_out_kernel(const __half* __restrict__ A0, const __half* __restrict__ A1,
                     const __half* __restrict__ Bw,
                     const float* __restrict__ bias,
                     float* __restrict__ out)
{
    extern __shared__ __align__(16) char smem[];
    const uint32_t sbase = smem_u32(smem);
    const int tid  = threadIdx.x;
    const int lane = tid & 31;
    const int wid  = tid >> 5;
    const int wm   = wid & 1;
    const int wn   = wid >> 1;
    const int m0   = blockIdx.y * 128;
    const int n0g  = blockIdx.x * 128;

    const int ar = tid >> 1;
    const int ac = tid & 1;
    const int fr = lane & 15;
    const int fc = (lane >> 4) * 16;
    const int r  = lane >> 2;
    const int c2 = (lane & 3) << 1;

    uint4 ua0, ua1, ub0, ub1;
    auto ldg = [&](int kt) {
        const int k0 = kt * 32;
        const __half* Asrc = (k0 < 256) ? A0 : A1;
        const int kc = k0 & 255;
        const __half* ap = Asrc + (size_t)(m0 + ar) * 256 + kc + ac * 16;
        ua0 = *(const uint4*)(ap);
        ua1 = *(const uint4*)(ap + 8);
        const __half* bp = Bw + (size_t)(n0g + ar) * 512 + k0 + ac * 16;
        ub0 = *(const uint4*)(bp);
        ub1 = *(const uint4*)(bp + 8);
    };
    auto sts = [&](int buf) {
        char* da = smem + buf * 2 * CH_BYTES + ar * CH_STRIDE + ac * 32;
        *(uint4*)(da)      = ua0;
        *(uint4*)(da + 16) = ua1;
        char* db = da + CH_BYTES;
        *(uint4*)(db)      = ub0;
        *(uint4*)(db + 16) = ub1;
    };

    float acc[4][4][4];
    #pragma unroll
    for (int i = 0; i < 4; i++)
        #pragma unroll
        for (int j = 0; j < 4; j++)
            #pragma unroll
            for (int c = 0; c < 4; c++) acc[i][j][c] = 0.f;

    ldg(0);
    sts(0);
    __syncthreads();

    #pragma unroll 1
    for (int kt = 0; kt < 16; kt++) {
        if (kt + 1 < 16) ldg(kt + 1);

        {
            const uint32_t abase = sbase + (kt & 1) * 2 * CH_BYTES;
            const uint32_t bbase = abase + CH_BYTES;
            #pragma unroll
            for (int s = 0; s < 2; s++) {
                uint32_t af[4][4], bf[2][4];
                #pragma unroll
                for (int mt = 0; mt < 4; mt++) {
                    int row = wm * 64 + mt * 16 + fr;
                    ldm_x4(af[mt], abase + row * CH_STRIDE + s * 32 + fc);
                }
                #pragma unroll
                for (int bi = 0; bi < 2; bi++) {
                    int row = wn * 32 + bi * 16 + fr;
                    ldm_x4(bf[bi], bbase + row * CH_STRIDE + s * 32 + fc);
                }
                #pragma unroll
                for (int mt = 0; mt < 4; mt++)
                    #pragma unroll
                    for (int nt2 = 0; nt2 < 4; nt2++) {
                        int bi = nt2 >> 1, od = nt2 & 1;
                        MMA_F16(acc[mt][nt2],
                                af[mt][0], af[mt][1], af[mt][2], af[mt][3],
                                bf[bi][od], bf[bi][od + 2]);
                    }
            }
        }

        if (kt + 1 < 16) sts((kt + 1) & 1);
        __syncthreads();
    }

    #pragma unroll
    for (int mt = 0; mt < 4; mt++) {
        int m = m0 + wm * 64 + mt * 16 + r;
        #pragma unroll
        for (int nt = 0; nt < 4; nt++) {
            int n = n0g + wn * 32 + nt * 8 + c2;
            float* a = acc[mt][nt];
            float b0 = bias[n], b1 = bias[n + 1];
            *(float2*)(out + (size_t)m * 256 + n)       = make_float2(a[0] + b0, a[1] + b1);
            *(float2*)(out + (size_t)(m + 8) * 256 + n) = make_float2(a[2] + b0, a[3] + b1);
        }
    }
}

// ---------------------------------------------------------------------------
// Spatial linear attention (attend over N=2048). Block = (bt, h), 8 warps.
// Phase 1: half2 HFMA2. Phase 2: m16n8k16 mma with B = [kvs^T | kss].
// ---------------------------------------------------------------------------
#define BVS 40   // half stride (80 B) for B / q staging rows
__global__ __launch_bounds__(256)
void spatial_attn_kernel(const __half* __restrict__ q, const __half* __restrict__ k,
                         const __half* __restrict__ v, __half* __restrict__ o)
{
    __shared__ float s_part[8][32][36];
    __shared__ float s_kvs[32][36];
    __shared__ float s_ksp[8][32];
    __shared__ float s_kss[32];
    __shared__ __align__(16) __half s_bv[48 * BVS];

    const int bt = blockIdx.x;
    const int h  = blockIdx.y;
    const int tid = threadIdx.x;
    const int w = tid >> 5, lane = tid & 31;

    const size_t baseBT = (size_t)bt * N_ * D_ + h * HD_;

    const int mg = lane >> 2;
    const int dg = lane & 3;

    const __half2 hz = __float2half2_rn(0.f);
    __half2 acc2[4][4];
    #pragma unroll
    for (int i = 0; i < 4; i++)
        #pragma unroll
        for (int j = 0; j < 4; j++) acc2[i][j] = hz;
    __half2 kss01 = hz, kss23 = hz;

    const int l0w = w * 256;
    #pragma unroll 4
    for (int l = l0w; l < l0w + 256; l++) {
        const __half* rk = k + baseBT + (size_t)l * D_;
        const __half* rv = v + baseBT + (size_t)l * D_;
        uint2 uk = *(const uint2*)(rk + mg * 4);
        uint4 uv = *(const uint4*)(rv + dg * 8);
        __half2 k01 = u2h2(uk.x), k23 = u2h2(uk.y);
        kss01 = __hadd2(kss01, k01);
        kss23 = __hadd2(kss23, k23);
        __half2 vj[4] = { u2h2(uv.x), u2h2(uv.y), u2h2(uv.z), u2h2(uv.w) };
        __half2 kb[4] = { __low2half2(k01), __high2half2(k01),
                          __low2half2(k23), __high2half2(k23) };
        #pragma unroll
        for (int i = 0; i < 4; i++)
            #pragma unroll
            for (int j = 0; j < 4; j++)
                acc2[i][j] = __hfma2(kb[i], vj[j], acc2[i][j]);
    }
    #pragma unroll
    for (int i = 0; i < 4; i++) {
        float2 p0 = __half22float2(acc2[i][0]);
        float2 p1 = __half22float2(acc2[i][1]);
        float2 p2 = __half22float2(acc2[i][2]);
        float2 p3 = __half22float2(acc2[i][3]);
        *(float4*)&s_part[w][mg*4+i][dg*8]     = make_float4(p0.x, p0.y, p1.x, p1.y);
        *(float4*)&s_part[w][mg*4+i][dg*8 + 4] = make_float4(p2.x, p2.y, p3.x, p3.y);
    }
    if (dg == 0) {
        float2 a = __half22float2(kss01);
        float2 b = __half22float2(kss23);
        s_ksp[w][mg*4+0] = a.x; s_ksp[w][mg*4+1] = a.y;
        s_ksp[w][mg*4+2] = b.x; s_ksp[w][mg*4+3] = b.y;
    }
    __syncthreads();

    // cross-warp reduce into s_kvs / s_kss
    {
        int m = tid >> 3, dd = (tid & 7) * 4;
        float4 s = make_float4(0.f, 0.f, 0.f, 0.f);
        #pragma unroll
        for (int wi = 0; wi < 8; wi++) {
            float4 p = *(const float4*)&s_part[wi][m][dd];
            s.x += p.x; s.y += p.y; s.z += p.z; s.w += p.w;
        }
        *(float4*)&s_kvs[m][dd] = s;
        if (tid < 32) {
            float s2 = 0.f;
            #pragma unroll
            for (int wi = 0; wi < 8; wi++) s2 += s_ksp[wi][tid];
            s_kss[tid] = s2;
        }
    }
    __syncthreads();

    // build B half matrix: rows 0..31 = kvs^T (d x mu), row 32 = kss
    for (int idx = tid; idx < 33 * 32; idx += 256) {
        int nn = idx >> 5, m = idx & 31;
        float val = (nn < 32) ? s_kvs[m][nn] : s_kss[m];
        s_bv[nn * BVS + m] = __float2half(val);
    }
    __syncthreads();

    const int fr = lane & 15;
    const int fc = (lane >> 4) * 16;
    const int r  = lane >> 2;
    const int c2 = (lane & 3) << 1;

    // hoist B fragments (shared across all 8 chunks)
    const uint32_t bvb = smem_u32(s_bv);
    uint32_t bf[3][2][4];
    #pragma unroll
    for (int bn = 0; bn < 3; bn++)
        #pragma unroll
        for (int s = 0; s < 2; s++)
            ldm_x4(bf[bn][s], bvb + (bn * 16 + fr) * (BVS * 2) + s * 32 + fc);

    __half* qs_h = (__half*)&s_part[w][0][0];
    const uint32_t qsb = smem_u32(qs_h);

    for (int c = 0; c < 8; c++) {
        const int l0 = l0w + c * 32;
        // stage q tile as half (raw copy)
        #pragma unroll
        for (int i2 = 0; i2 < 4; i2++) {
            int idx = lane + i2 * 32;          // 0..127
            int rr = idx >> 2, f = idx & 3;
            *(uint4*)(qs_h + rr * BVS + f * 8) =
                *(const uint4*)(q + baseBT + (size_t)(l0 + rr) * D_ + f * 8);
        }
        __syncwarp();

        uint32_t af[2][2][4];
        #pragma unroll
        for (int mt = 0; mt < 2; mt++)
            #pragma unroll
            for (int s = 0; s < 2; s++)
                ldm_x4(af[mt][s], qsb + (mt * 16 + fr) * (BVS * 2) + s * 32 + fc);

        float acc[2][5][4];
        #pragma unroll
        for (int mt = 0; mt < 2; mt++)
            #pragma unroll
            for (int nt = 0; nt < 5; nt++)
                #pragma unroll
                for (int cc = 0; cc < 4; cc++) acc[mt][nt][cc] = 0.f;

        #pragma unroll
        for (int mt = 0; mt < 2; mt++)
            #pragma unroll
            for (int nt = 0; nt < 5; nt++) {
                int bn = nt >> 1, od = nt & 1;
                #pragma unroll
                for (int s = 0; s < 2; s++)
                    MMA_F16(acc[mt][nt],
                            af[mt][s][0], af[mt][s][1], af[mt][s][2], af[mt][s][3],
                            bf[bn][s][od], bf[bn][s][od + 2]);
            }

        #pragma unroll
        for (int mt = 0; mt < 2; mt++) {
            float dlo = __shfl_sync(0xffffffffu, acc[mt][4][0], lane & 28);
            float dhi = __shfl_sync(0xffffffffu, acc[mt][4][2], lane & 28);
            float ilo = 1.f / fmaxf(dlo + (float)N_, 1e-5f);
            float ihi = 1.f / fmaxf(dhi + (float)N_, 1e-5f);
            int tlo = l0 + mt * 16 + r;
            int thi = tlo + 8;
            #pragma unroll
            for (int nt = 0; nt < 4; nt++) {
                int d = nt * 8 + c2;
                float2 vl = h2f2(*(const uint32_t*)(v + baseBT + (size_t)tlo * D_ + d));
                float2 vh = h2f2(*(const uint32_t*)(v + baseBT + (size_t)thi * D_ + d));
                float r0 = (acc[mt][nt][0] + (float)N_ * vl.x) * ilo;
                float r1 = (acc[mt][nt][1] + (float)N_ * vl.y) * ilo;
                float r2 = (acc[mt][nt][2] + (float)N_ * vh.x) * ihi;
                float r3 = (acc[mt][nt][3] + (float)N_ * vh.y) * ihi;
                *(uint32_t*)(o + baseBT + (size_t)tlo * D_ + d) = f2h2(r0, r1);
                *(uint32_t*)(o + baseBT + (size_t)thi * D_ + d) = f2h2(r2, r3);
            }
        }
        __syncwarp();
    }
}

// ---------------------------------------------------------------------------
// Temporal linear attention (attend over T=24). Block = (b, n), warp = head.
// Phase 1 half2 -> transposed half B directly; phase 2 mma.
// ---------------------------------------------------------------------------
#define TPH (48*BVS + 32*BVS)              // halfs per head: B(48 rows) + q(32 rows)
#define TSM_BYTES (8 * TPH * 2)            // 51200
__global__ __launch_bounds__(256)
void temporal_attn_kernel(const __half* __restrict__ q, const __half* __restrict__ k,
                          const __half* __restrict__ v, __half* __restrict__ o)
{
    extern __shared__ __align__(16) __half smh[];
    const int bn = blockIdx.x;
    const int b = bn >> 11;
    const int n = bn & 2047;
    const int tid = threadIdx.x;
    const int h = tid >> 5, lane = tid & 31;

    __half* bv_h = smh + h * TPH;
    __half* qs_h = bv_h + 48 * BVS;

    const size_t base = ((size_t)b * T_ * N_ + n) * D_ + h * HD_;
    const size_t sT = (size_t)N_ * D_;

    const int mg = lane >> 2;
    const int dg = lane & 3;

    const __half2 hz = __float2half2_rn(0.f);
    __half2 acc2[4][4];
    #pragma unroll
    for (int i = 0; i < 4; i++)
        #pragma unroll
        for (int j = 0; j < 4; j++) acc2[i][j] = hz;
    __half2 kss01 = hz, kss23 = hz;

    #pragma unroll
    for (int t = 0; t < T_; t++) {
        const __half* rk = k + base + (size_t)t * sT;
        const __half* rv = v + base + (size_t)t * sT;
        uint2 uk = *(const uint2*)(rk + mg * 4);
        uint4 uv = *(const uint4*)(rv + dg * 8);
        __half2 k01 = u2h2(uk.x), k23 = u2h2(uk.y);
        kss01 = __hadd2(kss01, k01);
        kss23 = __hadd2(kss23, k23);
        __half2 vj[4] = { u2h2(uv.x), u2h2(uv.y), u2h2(uv.z), u2h2(uv.w) };
        __half2 kb[4] = { __low2half2(k01), __high2half2(k01),
                          __low2half2(k23), __high2half2(k23) };
        #pragma unroll
        for (int i = 0; i < 4; i++)
            #pragma unroll
            for (int j = 0; j < 4; j++)
                acc2[i][j] = __hfma2(kb[i], vj[j], acc2[i][j]);
    }

    // store kvs transposed as half: bv_h[d][mu]  (mu = mg*4+i, d = dg*8+2j{,+1})
    #pragma unroll
    for (int i = 0; i < 4; i++)
        #pragma unroll
        for (int j = 0; j < 4; j++) {
            int mu = mg * 4 + i;
            int d  = dg * 8 + 2 * j;
            bv_h[d * BVS + mu]       = __low2half(acc2[i][j]);
            bv_h[(d + 1) * BVS + mu] = __high2half(acc2[i][j]);
        }
    if (dg == 0) {
        bv_h[32 * BVS + mg * 4 + 0] = __low2half(kss01);
        bv_h[32 * BVS + mg * 4 + 1] = __high2half(kss01);
        bv_h[32 * BVS + mg * 4 + 2] = __low2half(kss23);
        bv_h[32 * BVS + mg * 4 + 3] = __high2half(kss23);
    }
    // stage q (24 rows x 32 halfs, raw copy)
    #pragma unroll
    for (int i = 0; i < 3; i++) {
        int idx = lane + i * 32;               // 0..95
        int t = idx >> 2, f = idx & 3;
        *(uint4*)(qs_h + t * BVS + f * 8) =
            *(const uint4*)(q + base + (size_t)t * sT + f * 8);
    }
    __syncwarp();

    const int fr = lane & 15;
    const int fc = (lane >> 4) * 16;
    const int r  = lane >> 2;
    const int c2 = (lane & 3) << 1;

    const uint32_t bvb = smem_u32(bv_h);
    const uint32_t qsb = smem_u32(qs_h);

    uint32_t bf[3][2][4], af[2][2][4];
    #pragma unroll
    for (int bn2 = 0; bn2 < 3; bn2++)
        #pragma unroll
        for (int s = 0; s < 2; s++)
            ldm_x4(bf[bn2][s], bvb + (bn2 * 16 + fr) * (BVS * 2) + s * 32 + fc);
    #pragma unroll
    for (int mt = 0; mt < 2; mt++)
        #pragma unroll
        for (int s = 0; s < 2; s++)
            ldm_x4(af[mt][s], qsb + (mt * 16 + fr) * (BVS * 2) + s * 32 + fc);

    float acc[2][5][4];
    #pragma unroll
    for (int mt = 0; mt < 2; mt++)
        #pragma unroll
        for (int nt = 0; nt < 5; nt++)
            #pragma unroll
            for (int cc = 0; cc < 4; cc++) acc[mt][nt][cc] = 0.f;

    #pragma unroll
    for (int mt = 0; mt < 2; mt++)
        #pragma unroll
        for (int nt = 0; nt < 5; nt++) {
            int bn2 = nt >> 1, od = nt & 1;
            #pragma unroll
            for (int s = 0; s < 2; s++)
                MMA_F16(acc[mt][nt],
                        af[mt][s][0], af[mt][s][1], af[mt][s][2], af[mt][s][3],
                        bf[bn2][s][od], bf[bn2][s][od + 2]);
        }

    #pragma unroll
    for (int mt = 0; mt < 2; mt++) {
        float dlo = __shfl_sync(0xffffffffu, acc[mt][4][0], lane & 28);
        float dhi = __shfl_sync(0xffffffffu, acc[mt][4][2], lane & 28);
        float ilo = 1.f / fmaxf(dlo + (float)T_, 1e-5f);
        float ihi = 1.f / fmaxf(dhi + (float)T_, 1e-5f);
        int tlo = mt * 16 + r;
        int thi = tlo + 8;
        bool hiv = (thi < T_);                 // mt==1 hi tokens 24..31 invalid
        #pragma unroll
        for (int nt = 0; nt < 4; nt++) {
            int d = nt * 8 + c2;
            float2 vl = h2f2(*(const uint32_t*)(v + base + (size_t)tlo * sT + d));
            float r0 = (acc[mt][nt][0] + (float)T_ * vl.x) * ilo;
            float r1 = (acc[mt][nt][1] + (float)T_ * vl.y) * ilo;
            *(uint32_t*)(o + base + (size_t)tlo * sT + d) = f2h2(r0, r1);
            if (hiv) {
                float2 vh = h2f2(*(const uint32_t*)(v + base + (size_t)thi * sT + d));
                float r2 = (acc[mt][nt][2] + (float)T_ * vh.x) * ihi;
                float r3 = (acc[mt][nt][3] + (float)T_ * vh.y) * ihi;
                *(uint32_t*)(o + base + (size_t)thi * sT + d) = f2h2(r2, r3);
            }
        }
    }
}

// ---------------------------------------------------------------------------
extern "C" void kernel_launch(void* const* d_in, const int* in_sizes, int n_in,
                              void* d_out, int out_size)
{
    const float* x     = (const float*)d_in[0];
    const float* w_qkv = (const float*)d_in[1];
    const float* w_out = (const float*)d_in[2];
    const float* b_out = (const float*)d_in[3];
    float* out = (float*)d_out;

    __half *q, *k, *v, *os, *ot, *wqh, *woh;
    cudaGetSymbolAddress((void**)&q,   g_q);
    cudaGetSymbolAddress((void**)&k,   g_k);
    cudaGetSymbolAddress((void**)&v,   g_v);
    cudaGetSymbolAddress((void**)&os,  g_os);
    cudaGetSymbolAddress((void**)&ot,  g_ot);
    cudaGetSymbolAddress((void**)&wqh, g_wqh);
    cudaGetSymbolAddress((void**)&woh, g_woh);

    cudaFuncSetAttribute(gemm_qkv_kernel,
                         cudaFuncAttributeMaxDynamicSharedMemorySize, G1_SMEM);
    cudaFuncSetAttribute(gemm_out_kernel,
                         cudaFuncAttributeMaxDynamicSharedMemorySize, G2_SMEM);
    cudaFuncSetAttribute(temporal_attn_kernel,
                         cudaFuncAttributeMaxDynamicSharedMemorySize, TSM_BYTES);

    // 0) convert weights to fp16 scratch
    {
        int total = (768 * 256 + 256 * 512) / 2;
        cvt_weights_kernel<<<(total + 255) / 256, 256>>>(w_qkv, w_out, wqh, woh);
    }
    // 1) QKV projection (fp16 mma, A-resident) + fused q/k l2norm
    gemm_qkv_kernel<<<MTOK / 128, 256, G1_SMEM>>>(x, wqh, q, k, v);

    // 2) spatial attention
    {
        dim3 grid(B_ * T_, H_);
        spatial_attn_kernel<<<grid, 256>>>(q, k, v, os);
    }
    // 3) temporal attention
    temporal_attn_kernel<<<B_ * N_, 256, TSM_BYTES>>>(q, k, v, ot);

    // 4) output projection + bias (fp16 mma, dual-A concat)
    {
        dim3 grid(2, MTOK / 128);
        gemm_out_kernel<<<grid, 256, G2_SMEM>>>(os, ot, woh, b_out, out);
    }
}

// round 12
// speedup vs baseline: 1.4362x; 1.0814x over previous
#include <cuda_runtime.h>
#include <cuda_fp16.h>
#include <math.h>
#include <stdint.h>

#define B_  4
#define T_  24
#define N_  2048
#define D_  256
#define H_  8
#define HD_ 32
#define MTOK (B_*T_*N_)           // 196608 tokens
#define ELEMS ((size_t)MTOK * D_) // 50,331,648

// Scratch (device globals; allocation-free per harness rules). All fp16.
__device__ __half g_q [ELEMS];
__device__ __half g_k [ELEMS];
__device__ __half g_v [ELEMS];
__device__ __half g_os[ELEMS];
__device__ __half g_ot[ELEMS];
__device__ __half g_wqh[768*256];
__device__ __half g_woh[256*512];

// ---------------------------------------------------------------------------
// helpers
// ---------------------------------------------------------------------------
__device__ __forceinline__ uint32_t smem_u32(const void* p) {
    uint32_t a;
    asm("{ .reg .u64 t; cvta.to.shared.u64 t, %1; cvt.u32.u64 %0, t; }"
        : "=r"(a) : "l"(p));
    return a;
}
__device__ __forceinline__ uint32_t f2h2(float a, float b) {
    __half2 h = __floats2half2_rn(a, b);
    return *(uint32_t*)&h;
}
__device__ __forceinline__ uint2 f4h(float4 v) {
    return make_uint2(f2h2(v.x, v.y), f2h2(v.z, v.w));
}
__device__ __forceinline__ float2 h2f2(uint32_t h) {
    return __half22float2(*(__half2*)&h);
}
__device__ __forceinline__ __half2 u2h2(uint32_t u) { return *(__half2*)&u; }
__device__ __forceinline__ void ldm_x4(uint32_t* r, uint32_t addr) {
    asm volatile("ldmatrix.sync.aligned.m8n8.x4.shared.b16 {%0,%1,%2,%3}, [%4];"
                 : "=r"(r[0]), "=r"(r[1]), "=r"(r[2]), "=r"(r[3]) : "r"(addr));
}
__device__ __forceinline__ void ldm_x4_t(uint32_t* r, uint32_t addr) {
    asm volatile("ldmatrix.sync.aligned.m8n8.x4.trans.shared.b16 {%0,%1,%2,%3}, [%4];"
                 : "=r"(r[0]), "=r"(r[1]), "=r"(r[2]), "=r"(r[3]) : "r"(addr));
}
#define MMA_F16(d, a0, a1, a2, a3, b0, b1)                                    \
    asm volatile("mma.sync.aligned.m16n8k16.row.col.f32.f16.f16.f32 "         \
                 "{%0,%1,%2,%3}, {%4,%5,%6,%7}, {%8,%9}, {%0,%1,%2,%3};"      \
                 : "+f"(d[0]), "+f"(d[1]), "+f"(d[2]), "+f"(d[3])             \
                 : "r"(a0), "r"(a1), "r"(a2), "r"(a3), "r"(b0), "r"(b1))

// Row strides: 80B (chunk tiles) and 528B (resident A). Both ≡16 (mod 128).
#define CH_STRIDE 80
#define CH_BYTES  (128*CH_STRIDE)
#define AR_STRIDE 528
#define AR_BYTES  (128*AR_STRIDE)

// ---------------------------------------------------------------------------
// weight pre-conversion: f32 -> f16 (once per launch)
// ---------------------------------------------------------------------------
__global__ void cvt_weights_kernel(const float* __restrict__ wq,
                                   const float* __restrict__ wo,
                                   __half* __restrict__ wqh,
                                   __half* __restrict__ woh)
{
    int i = blockIdx.x * blockDim.x + threadIdx.x;
    const int NQ = 768 * 256 / 2;
    const int NO = 256 * 512 / 2;
    if (i < NQ) {
        float2 f = *(const float2*)(wq + i * 2);
        *(uint32_t*)(wqh + i * 2) = f2h2(f.x, f.y);
    } else if (i < NQ + NO) {
        int j = i - NQ;
        float2 f = *(const float2*)(wo + j * 2);
        *(uint32_t*)(woh + j * 2) = f2h2(f.x, f.y);
    }
}

// ===========================================================================
// GEMM1 (A-resident, fp16): qkv[M,768] = x[M,256] * w_qkv[768,256]^T
// ===========================================================================
#define G1_SMEM (AR_BYTES + 2*CH_BYTES)   // 88064

__global__ __launch_bounds__(256, 2)
void gemm_qkv_kernel(const float* __restrict__ A, const __half* __restrict__ Bw,
                     __half* __restrict__ outq, __half* __restrict__ outk,
                     __half* __restrict__ outv)
{
    extern __shared__ __align__(16) char smem[];
    const uint32_t sbase = smem_u32(smem);
    const int tid  = threadIdx.x;
    const int lane = tid & 31;
    const int wid  = tid >> 5;
    const int wm   = wid & 1;
    const int wn   = wid >> 1;
    const int m0   = blockIdx.x * 128;

    const int ar = tid >> 1;
    const int ac = tid & 1;
    const int fr = lane & 15;
    const int fc = (lane >> 4) * 16;
    const int r  = lane >> 2;
    const int c2 = (lane & 3) << 1;

    #pragma unroll
    for (int j = 0; j < 8; j++) {
        const float* ap = A + (size_t)(m0 + ar) * 256 + (ac * 8 + j) * 16;
        uint2 h0 = f4h(*(const float4*)(ap + 0));
        uint2 h1 = f4h(*(const float4*)(ap + 4));
        uint2 h2 = f4h(*(const float4*)(ap + 8));
        uint2 h3 = f4h(*(const float4*)(ap + 12));
        char* dst = smem + ar * AR_STRIDE + (ac * 8 + j) * 32;
        *(uint4*)(dst)      = make_uint4(h0.x, h0.y, h1.x, h1.y);
        *(uint4*)(dst + 16) = make_uint4(h2.x, h2.y, h3.x, h3.y);
    }

    uint4 hb0, hb1;
    auto ldgB = [&](int it) {
        const int nt = it >> 3, kt = it & 7;
        const __half* bp = Bw + (size_t)(nt * 128 + ar) * 256 + kt * 32 + ac * 16;
        hb0 = *(const uint4*)(bp);
        hb1 = *(const uint4*)(bp + 8);
    };
    auto stsB = [&](int buf) {
        char* dst = smem + AR_BYTES + buf * CH_BYTES + ar * CH_STRIDE + ac * 32;
        *(uint4*)(dst)      = hb0;
        *(uint4*)(dst + 16) = hb1;
    };

    float acc[4][4][4];
    #pragma unroll
    for (int i = 0; i < 4; i++)
        #pragma unroll
        for (int j = 0; j < 4; j++)
            #pragma unroll
            for (int c = 0; c < 4; c++) acc[i][j][c] = 0.f;

    ldgB(0);
    stsB(0);
    __syncthreads();

    #pragma unroll 1
    for (int it = 0; it < 48; it++) {
        if (it + 1 < 48) ldgB(it + 1);

        {
            const int kt = it & 7;
            const uint32_t abase = sbase + kt * 64;
            const uint32_t bbase = sbase + AR_BYTES + (it & 1) * CH_BYTES;
            #pragma unroll
            for (int s = 0; s < 2; s++) {
                uint32_t af[4][4], bf[2][4];
                #pragma unroll
                for (int mt = 0; mt < 4; mt++) {
                    int row = wm * 64 + mt * 16 + fr;
                    ldm_x4(af[mt], abase + row * AR_STRIDE + s * 32 + fc);
                }
                #pragma unroll
                for (int bi = 0; bi < 2; bi++) {
                    int row = wn * 32 + bi * 16 + fr;
                    ldm_x4(bf[bi], bbase + row * CH_STRIDE + s * 32 + fc);
                }
                #pragma unroll
                for (int mt = 0; mt < 4; mt++)
                    #pragma unroll
                    for (int nt2 = 0; nt2 < 4; nt2++) {
                        int bi = nt2 >> 1, od = nt2 & 1;
                        MMA_F16(acc[mt][nt2],
                                af[mt][0], af[mt][1], af[mt][2], af[mt][3],
                                bf[bi][od], bf[bi][od + 2]);
                    }
            }
        }

        if ((it & 7) == 7) {
            const int n0g = (it >> 3) * 128;
            const int sel = n0g >> 8;

            if (sel < 2) {
                #pragma unroll
                for (int mt = 0; mt < 4; mt++) {
                    float sslo = 0.f, sshi = 0.f;
                    #pragma unroll
                    for (int nt2 = 0; nt2 < 4; nt2++) {
                        sslo = fmaf(acc[mt][nt2][0], acc[mt][nt2][0], sslo);
                        sslo = fmaf(acc[mt][nt2][1], acc[mt][nt2][1], sslo);
                        sshi = fmaf(acc[mt][nt2][2], acc[mt][nt2][2], sshi);
                        sshi = fmaf(acc[mt][nt2][3], acc[mt][nt2][3], sshi);
                    }
                    sslo += __shfl_xor_sync(0xffffffffu, sslo, 1);
                    sslo += __shfl_xor_sync(0xffffffffu, sslo, 2);
                    sshi += __shfl_xor_sync(0xffffffffu, sshi, 1);
                    sshi += __shfl_xor_sync(0xffffffffu, sshi, 2);
                    float slo = 1.f / fmaxf(sqrtf(sslo), 1e-12f);
                    float shi = 1.f / fmaxf(sqrtf(sshi), 1e-12f);
                    #pragma unroll
                    for (int nt2 = 0; nt2 < 4; nt2++) {
                        acc[mt][nt2][0] *= slo; acc[mt][nt2][1] *= slo;
                        acc[mt][nt2][2] *= shi; acc[mt][nt2][3] *= shi;
                    }
                }
            }

            __half* dst = (sel == 0) ? outq : ((sel == 1) ? outk : outv);
            #pragma unroll
            for (int mt = 0; mt < 4; mt++) {
                int m = m0 + wm * 64 + mt * 16 + r;
                #pragma unroll
                for (int nt2 = 0; nt2 < 4; nt2++) {
                    int col = ((n0g + wn * 32 + nt2 * 8 + c2) & 255);
                    float* a = acc[mt][nt2];
                    *(uint32_t*)(dst + (size_t)m * 256 + col)       = f2h2(a[0], a[1]);
                    *(uint32_t*)(dst + (size_t)(m + 8) * 256 + col) = f2h2(a[2], a[3]);
                    a[0] = a[1] = a[2] = a[3] = 0.f;
                }
            }
        }

        if (it + 1 < 48) stsB((it + 1) & 1);
        __syncthreads();
    }
}

// ===========================================================================
// GEMM2 (fp16 in / f32 out): out = [os|ot] * w_out^T + b
// ===========================================================================
#define G2_SMEM (4*CH_BYTES)   // 40960

__global__ __launch_bounds__(256, 2)
void gemm_out_kernel(const __half* __restrict__ A0, const __half* __restrict__ A1,
                     const __half* __restrict__ Bw,
                     const float* __restrict__ bias,
                     float* __restrict__ out)
{
    extern __shared__ __align__(16) char smem[];
    const uint32_t sbase = smem_u32(smem);
    const int tid  = threadIdx.x;
    const int lane = tid & 31;
    const int wid  = tid >> 5;
    const int wm   = wid & 1;
    const int wn   = wid >> 1;
    const int m0   = blockIdx.y * 128;
    const int n0g  = blockIdx.x * 128;

    const int ar = tid >> 1;
    const int ac = tid & 1;
    const int fr = lane & 15;
    const int fc = (lane >> 4) * 16;
    const int r  = lane >> 2;
    const int c2 = (lane & 3) << 1;

    uint4 ua0, ua1, ub0, ub1;
    auto ldg = [&](int kt) {
        const int k0 = kt * 32;
        const __half* Asrc = (k0 < 256) ? A0 : A1;
        const int kc = k0 & 255;
        const __half* ap = Asrc + (size_t)(m0 + ar) * 256 + kc + ac * 16;
        ua0 = *(const uint4*)(ap);
        ua1 = *(const uint4*)(ap + 8);
        const __half* bp = Bw + (size_t)(n0g + ar) * 512 + k0 + ac * 16;
        ub0 = *(const uint4*)(bp);
        ub1 = *(const uint4*)(bp + 8);
    };
    auto sts = [&](int buf) {
        char* da = smem + buf * 2 * CH_BYTES + ar * CH_STRIDE + ac * 32;
        *(uint4*)(da)      = ua0;
        *(uint4*)(da + 16) = ua1;
        char* db = da + CH_BYTES;
        *(uint4*)(db)      = ub0;
        *(uint4*)(db + 16) = ub1;
    };

    float acc[4][4][4];
    #pragma unroll
    for (int i = 0; i < 4; i++)
        #pragma unroll
        for (int j = 0; j < 4; j++)
            #pragma unroll
            for (int c = 0; c < 4; c++) acc[i][j][c] = 0.f;

    ldg(0);
    sts(0);
    __syncthreads();

    #pragma unroll 1
    for (int kt = 0; kt < 16; kt++) {
        if (kt + 1 < 16) ldg(kt + 1);

        {
            const uint32_t abase = sbase + (kt & 1) * 2 * CH_BYTES;
            const uint32_t bbase = abase + CH_BYTES;
            #pragma unroll
            for (int s = 0; s < 2; s++) {
                uint32_t af[4][4], bf[2][4];
                #pragma unroll
                for (int mt = 0; mt < 4; mt++) {
                    int row = wm * 64 + mt * 16 + fr;
                    ldm_x4(af[mt], abase + row * CH_STRIDE + s * 32 + fc);
                }
                #pragma unroll
                for (int bi = 0; bi < 2; bi++) {
                    int row = wn * 32 + bi * 16 + fr;
                    ldm_x4(bf[bi], bbase + row * CH_STRIDE + s * 32 + fc);
                }
                #pragma unroll
                for (int mt = 0; mt < 4; mt++)
                    #pragma unroll
                    for (int nt2 = 0; nt2 < 4; nt2++) {
                        int bi = nt2 >> 1, od = nt2 & 1;
                        MMA_F16(acc[mt][nt2],
                                af[mt][0], af[mt][1], af[mt][2], af[mt][3],
                                bf[bi][od], bf[bi][od + 2]);
                    }
            }
        }

        if (kt + 1 < 16) sts((kt + 1) & 1);
        __syncthreads();
    }

    #pragma unroll
    for (int mt = 0; mt < 4; mt++) {
        int m = m0 + wm * 64 + mt * 16 + r;
        #pragma unroll
        for (int nt = 0; nt < 4; nt++) {
            int n = n0g + wn * 32 + nt * 8 + c2;
            float* a = acc[mt][nt];
            float b0 = bias[n], b1 = bias[n + 1];
            *(float2*)(out + (size_t)m * 256 + n)       = make_float2(a[0] + b0, a[1] + b1);
            *(float2*)(out + (size_t)(m + 8) * 256 + n) = make_float2(a[2] + b0, a[3] + b1);
        }
    }
}

// ---------------------------------------------------------------------------
// Spatial linear attention (attend over N=2048). Block = (bt, h), 8 warps.
// Phase 1: mma via ldmatrix.trans — kvs = k^T [v | 1], kss = column 32.
// Phase 2: mma with B = [kvs^T | kss].
// ---------------------------------------------------------------------------
#define BVS 40   // half stride (80 B) for phase-2 B / q staging rows
#define KST_S 40 // k stage stride (halfs) = 80 B (16B-aligned, ≡16 mod 128)
#define VST_S 56 // v stage stride (halfs) = 112 B (16B-aligned; 112*r mod 128 distinct over 8 rows)
__global__ __launch_bounds__(256)
void spatial_attn_kernel(const __half* __restrict__ q, const __half* __restrict__ k,
                         const __half* __restrict__ v, __half* __restrict__ o)
{
    __shared__ float s_part[8][32][36];
    __shared__ float s_kvs[32][36];
    __shared__ float s_kss[32];
    __shared__ __align__(16) __half s_bv[48 * BVS];

    const int bt = blockIdx.x;
    const int h  = blockIdx.y;
    const int tid = threadIdx.x;
    const int w = tid >> 5, lane = tid & 31;

    const size_t baseBT = (size_t)bt * N_ * D_ + h * HD_;
    const int l0w = w * 256;

    // per-warp staging aliased inside s_part[w] (4608 B):
    // kst: 16 rows x KST_S halfs (1280 B), vst: 16 rows x VST_S halfs (1792 B)
    char* wb = (char*)&s_part[w][0][0];
    __half* kst = (__half*)wb;
    __half* vst = (__half*)(wb + 16 * KST_S * 2);
    const uint32_t kstb = smem_u32(kst);
    const uint32_t vstb = smem_u32(vst);

    // ones column (kss accumulator feed); cols 33..47 junk -> unused acc cols
    if (lane < 16) vst[lane * VST_S + 32] = __float2half(1.f);
    __syncwarp();

    // ldmatrix.trans lane addressing: row=(lane&7)+(lane>=16)*8, col16=(lane>>3)&1
    const int fr_t = (lane & 7) + ((lane >> 4) & 1) * 8;
    const int fc_t = ((lane >> 3) & 1) * 16;

    float acc1[2][5][4];
    #pragma unroll
    for (int mt = 0; mt < 2; mt++)
        #pragma unroll
        for (int nt = 0; nt < 5; nt++)
            #pragma unroll
            for (int c = 0; c < 4; c++) acc1[mt][nt][c] = 0.f;

    const int crow = lane >> 2;          // 0..7
    const int cq4  = (lane & 3) * 8;     // half offset in row (16B-aligned)

    uint4 kr2[2], vr2[2];
    auto ldgkv = [&](int c16) {
        int l0c = l0w + c16 * 16;
        #pragma unroll
        for (int i = 0; i < 2; i++) {
            int row = l0c + crow + i * 8;
            kr2[i] = *(const uint4*)(k + baseBT + (size_t)row * D_ + cq4);
            vr2[i] = *(const uint4*)(v + baseBT + (size_t)row * D_ + cq4);
        }
    };
    auto stskv = [&]() {
        #pragma unroll
        for (int i = 0; i < 2; i++) {
            int row = crow + i * 8;
            *(uint4*)(kst + row * KST_S + cq4) = kr2[i];
            *(uint4*)(vst + row * VST_S + cq4) = vr2[i];
        }
    };

    ldgkv(0); stskv(); __syncwarp();
    #pragma unroll 1
    for (int c16 = 0; c16 < 16; c16++) {
        if (c16 + 1 < 16) ldgkv(c16 + 1);

        uint32_t afr[2][4], bfr[3][4];
        ldm_x4_t(afr[0], kstb + fr_t * (KST_S * 2) + fc_t);
        ldm_x4_t(afr[1], kstb + fr_t * (KST_S * 2) + 32 + fc_t);
        ldm_x4_t(bfr[0], vstb + fr_t * (VST_S * 2) + fc_t);
        ldm_x4_t(bfr[1], vstb + fr_t * (VST_S * 2) + 32 + fc_t);
        ldm_x4_t(bfr[2], vstb + fr_t * (VST_S * 2) + 64 + fc_t);

        #pragma unroll
        for (int mt = 0; mt < 2; mt++)
            #pragma unroll
            for (int nt = 0; nt < 5; nt++) {
                int bn = nt >> 1, od = nt & 1;
                MMA_F16(acc1[mt][nt],
                        afr[mt][0], afr[mt][1], afr[mt][2], afr[mt][3],
                        bfr[bn][od], bfr[bn][od + 2]);
            }

        if (c16 + 1 < 16) {
            __syncwarp();
            stskv();
        }
        __syncwarp();
    }

    // write per-warp kvs (f32) + kss (col 32) to s_part[w] (staging now dead)
    {
        const int r = lane >> 2;
        const int c2l = (lane & 3) << 1;
        #pragma unroll
        for (int mt = 0; mt < 2; mt++) {
            #pragma unroll
            for (int nt = 0; nt < 4; nt++) {
                *(float2*)&s_part[w][mt*16 + r][nt*8 + c2l] =
                    make_float2(acc1[mt][nt][0], acc1[mt][nt][1]);
                *(float2*)&s_part[w][mt*16 + r + 8][nt*8 + c2l] =
                    make_float2(acc1[mt][nt][2], acc1[mt][nt][3]);
            }
            if (c2l == 0) {
                s_part[w][mt*16 + r][32]     = acc1[mt][4][0];
                s_part[w][mt*16 + r + 8][32] = acc1[mt][4][2];
            }
        }
    }
    __syncthreads();

    // cross-warp reduce into s_kvs / s_kss
    {
        int m = tid >> 3, dd = (tid & 7) * 4;
        float4 s = make_float4(0.f, 0.f, 0.f, 0.f);
        #pragma unroll
        for (int wi = 0; wi < 8; wi++) {
            float4 p = *(const float4*)&s_part[wi][m][dd];
            s.x += p.x; s.y += p.y; s.z += p.z; s.w += p.w;
        }
        *(float4*)&s_kvs[m][dd] = s;
        if (tid < 32) {
            float s2 = 0.f;
            #pragma unroll
            for (int wi = 0; wi < 8; wi++) s2 += s_part[wi][tid][32];
            s_kss[tid] = s2;
        }
    }
    __syncthreads();

    // build phase-2 B half matrix: rows 0..31 = kvs^T (d x mu), row 32 = kss
    for (int idx = tid; idx < 33 * 32; idx += 256) {
        int nn = idx >> 5, m = idx & 31;
        float val = (nn < 32) ? s_kvs[m][nn] : s_kss[m];
        s_bv[nn * BVS + m] = __float2half(val);
    }
    __syncthreads();

    const int fr = lane & 15;
    const int fc = (lane >> 4) * 16;
    const int r  = lane >> 2;
    const int c2 = (lane & 3) << 1;

    // hoist B fragments (shared across all 8 chunks)
    const uint32_t bvb = smem_u32(s_bv);
    uint32_t bf[3][2][4];
    #pragma unroll
    for (int bn = 0; bn < 3; bn++)
        #pragma unroll
        for (int s = 0; s < 2; s++)
            ldm_x4(bf[bn][s], bvb + (bn * 16 + fr) * (BVS * 2) + s * 32 + fc);

    __half* qs_h = (__half*)&s_part[w][0][0];
    const uint32_t qsb = smem_u32(qs_h);

    for (int c = 0; c < 8; c++) {
        const int l0 = l0w + c * 32;
        // stage q tile as half (raw copy)
        #pragma unroll
        for (int i2 = 0; i2 < 4; i2++) {
            int idx = lane + i2 * 32;          // 0..127
            int rr = idx >> 2, f = idx & 3;
            *(uint4*)(qs_h + rr * BVS + f * 8) =
                *(const uint4*)(q + baseBT + (size_t)(l0 + rr) * D_ + f * 8);
        }
        __syncwarp();

        uint32_t af[2][2][4];
        #pragma unroll
        for (int mt = 0; mt < 2; mt++)
            #pragma unroll
            for (int s = 0; s < 2; s++)
                ldm_x4(af[mt][s], qsb + (mt * 16 + fr) * (BVS * 2) + s * 32 + fc);

        float acc[2][5][4];
        #pragma unroll
        for (int mt = 0; mt < 2; mt++)
            #pragma unroll
            for (int nt = 0; nt < 5; nt++)
                #pragma unroll
                for (int cc = 0; cc < 4; cc++) acc[mt][nt][cc] = 0.f;

        #pragma unroll
        for (int mt = 0; mt < 2; mt++)
            #pragma unroll
            for (int nt = 0; nt < 5; nt++) {
                int bn = nt >> 1, od = nt & 1;
                #pragma unroll
                for (int s = 0; s < 2; s++)
                    MMA_F16(acc[mt][nt],
                            af[mt][s][0], af[mt][s][1], af[mt][s][2], af[mt][s][3],
                            bf[bn][s][od], bf[bn][s][od + 2]);
            }

        #pragma unroll
        for (int mt = 0; mt < 2; mt++) {
            float dlo = __shfl_sync(0xffffffffu, acc[mt][4][0], lane & 28);
            float dhi = __shfl_sync(0xffffffffu, acc[mt][4][2], lane & 28);
            float ilo = 1.f / fmaxf(dlo + (float)N_, 1e-5f);
            float ihi = 1.f / fmaxf(dhi + (float)N_, 1e-5f);
            int tlo = l0 + mt * 16 + r;
            int thi = tlo + 8;
            #pragma unroll
            for (int nt = 0; nt < 4; nt++) {
                int d = nt * 8 + c2;
                float2 vl = h2f2(*(const uint32_t*)(v + baseBT + (size_t)tlo * D_ + d));
                float2 vh = h2f2(*(const uint32_t*)(v + baseBT + (size_t)thi * D_ + d));
                float r0 = (acc[mt][nt][0] + (float)N_ * vl.x) * ilo;
                float r1 = (acc[mt][nt][1] + (float)N_ * vl.y) * ilo;
                float r2 = (acc[mt][nt][2] + (float)N_ * vh.x) * ihi;
                float r3 = (acc[mt][nt][3] + (float)N_ * vh.y) * ihi;
                *(uint32_t*)(o + baseBT + (size_t)tlo * D_ + d) = f2h2(r0, r1);
                *(uint32_t*)(o + baseBT + (size_t)thi * D_ + d) = f2h2(r2, r3);
            }
        }
        __syncwarp();
    }
}

// ---------------------------------------------------------------------------
// Temporal linear attention (attend over T=24). Block = (b, n), warp = head.
// Phase 1 half2 -> transposed half B directly; phase 2 mma.
// ---------------------------------------------------------------------------
#define TPH (48*BVS + 32*BVS)              // halfs per head: B(48 rows) + q(32 rows)
#define TSM_BYTES (8 * TPH * 2)            // 51200
__global__ __launch_bounds__(256)
void temporal_attn_kernel(const __half* __restrict__ q, const __half* __restrict__ k,
                          const __half* __restrict__ v, __half* __restrict__ o)
{
    extern __shared__ __align__(16) __half smh[];
    const int bn = blockIdx.x;
    const int b = bn >> 11;
    const int n = bn & 2047;
    const int tid = threadIdx.x;
    const int h = tid >> 5, lane = tid & 31;

    __half* bv_h = smh + h * TPH;
    __half* qs_h = bv_h + 48 * BVS;

    const size_t base = ((size_t)b * T_ * N_ + n) * D_ + h * HD_;
    const size_t sT = (size_t)N_ * D_;

    const int mg = lane >> 2;
    const int dg = lane & 3;

    const __half2 hz = __float2half2_rn(0.f);
    __half2 acc2[4][4];
    #pragma unroll
    for (int i = 0; i < 4; i++)
        #pragma unroll
        for (int j = 0; j < 4; j++) acc2[i][j] = hz;
    __half2 kss01 = hz, kss23 = hz;

    #pragma unroll
    for (int t = 0; t < T_; t++) {
        const __half* rk = k + base + (size_t)t * sT;
        const __half* rv = v + base + (size_t)t * sT;
        uint2 uk = *(const uint2*)(rk + mg * 4);
        uint4 uv = *(const uint4*)(rv + dg * 8);
        __half2 k01 = u2h2(uk.x), k23 = u2h2(uk.y);
        kss01 = __hadd2(kss01, k01);
        kss23 = __hadd2(kss23, k23);
        __half2 vj[4] = { u2h2(uv.x), u2h2(uv.y), u2h2(uv.z), u2h2(uv.w) };
        __half2 kb[4] = { __low2half2(k01), __high2half2(k01),
                          __low2half2(k23), __high2half2(k23) };
        #pragma unroll
        for (int i = 0; i < 4; i++)
            #pragma unroll
            for (int j = 0; j < 4; j++)
                acc2[i][j] = __hfma2(kb[i], vj[j], acc2[i][j]);
    }

    #pragma unroll
    for (int i = 0; i < 4; i++)
        #pragma unroll
        for (int j = 0; j < 4; j++) {
            int mu = mg * 4 + i;
            int d  = dg * 8 + 2 * j;
            bv_h[d * BVS + mu]       = __low2half(acc2[i][j]);
            bv_h[(d + 1) * BVS + mu] = __high2half(acc2[i][j]);
        }
    if (dg == 0) {
        bv_h[32 * BVS + mg * 4 + 0] = __low2half(kss01);
        bv_h[32 * BVS + mg * 4 + 1] = __high2half(kss01);
        bv_h[32 * BVS + mg * 4 + 2] = __low2half(kss23);
        bv_h[32 * BVS + mg * 4 + 3] = __high2half(kss23);
    }
    #pragma unroll
    for (int i = 0; i < 3; i++) {
        int idx = lane + i * 32;               // 0..95
        int t = idx >> 2, f = idx & 3;
        *(uint4*)(qs_h + t * BVS + f * 8) =
            *(const uint4*)(q + base + (size_t)t * sT + f * 8);
    }
    __syncwarp();

    const int fr = lane & 15;
    const int fc = (lane >> 4) * 16;
    const int r  = lane >> 2;
    const int c2 = (lane & 3) << 1;

    const uint32_t bvb = smem_u32(bv_h);
    const uint32_t qsb = smem_u32(qs_h);

    uint32_t bf[3][2][4], af[2][2][4];
    #pragma unroll
    for (int bn2 = 0; bn2 < 3; bn2++)
        #pragma unroll
        for (int s = 0; s < 2; s++)
            ldm_x4(bf[bn2][s], bvb + (bn2 * 16 + fr) * (BVS * 2) + s * 32 + fc);
    #pragma unroll
    for (int mt = 0; mt < 2; mt++)
        #pragma unroll
        for (int s = 0; s < 2; s++)
            ldm_x4(af[mt][s], qsb + (mt * 16 + fr) * (BVS * 2) + s * 32 + fc);

    float acc[2][5][4];
    #pragma unroll
    for (int mt = 0; mt < 2; mt++)
        #pragma unroll
        for (int nt = 0; nt < 5; nt++)
            #pragma unroll
            for (int cc = 0; cc < 4; cc++) acc[mt][nt][cc] = 0.f;

    #pragma unroll
    for (int mt = 0; mt < 2; mt++)
        #pragma unroll
        for (int nt = 0; nt < 5; nt++) {
            int bn2 = nt >> 1, od = nt & 1;
            #pragma unroll
            for (int s = 0; s < 2; s++)
                MMA_F16(acc[mt][nt],
                        af[mt][s][0], af[mt][s][1], af[mt][s][2], af[mt][s][3],
                        bf[bn2][s][od], bf[bn2][s][od + 2]);
        }

    #pragma unroll
    for (int mt = 0; mt < 2; mt++) {
        float dlo = __shfl_sync(0xffffffffu, acc[mt][4][0], lane & 28);
        float dhi = __shfl_sync(0xffffffffu, acc[mt][4][2], lane & 28);
        float ilo = 1.f / fmaxf(dlo + (float)T_, 1e-5f);
        float ihi = 1.f / fmaxf(dhi + (float)T_, 1e-5f);
        int tlo = mt * 16 + r;
        int thi = tlo + 8;
        bool hiv = (thi < T_);
        #pragma unroll
        for (int nt = 0; nt < 4; nt++) {
            int d = nt * 8 + c2;
            float2 vl = h2f2(*(const uint32_t*)(v + base + (size_t)tlo * sT + d));
            float r0 = (acc[mt][nt][0] + (float)T_ * vl.x) * ilo;
            float r1 = (acc[mt][nt][1] + (float)T_ * vl.y) * ilo;
            *(uint32_t*)(o + base + (size_t)tlo * sT + d) = f2h2(r0, r1);
            if (hiv) {
                float2 vh = h2f2(*(const uint32_t*)(v + base + (size_t)thi * sT + d));
                float r2 = (acc[mt][nt][2] + (float)T_ * vh.x) * ihi;
                float r3 = (acc[mt][nt][3] + (float)T_ * vh.y) * ihi;
                *(uint32_t*)(o + base + (size_t)thi * sT + d) = f2h2(r2, r3);
            }
        }
    }
}

// ---------------------------------------------------------------------------
extern "C" void kernel_launch(void* const* d_in, const int* in_sizes, int n_in,
                              void* d_out, int out_size)
{
    const float* x     = (const float*)d_in[0];
    const float* w_qkv = (const float*)d_in[1];
    const float* w_out = (const float*)d_in[2];
    const float* b_out = (const float*)d_in[3];
    float* out = (float*)d_out;

    __half *q, *k, *v, *os, *ot, *wqh, *woh;
    cudaGetSymbolAddress((void**)&q,   g_q);
    cudaGetSymbolAddress((void**)&k,   g_k);
    cudaGetSymbolAddress((void**)&v,   g_v);
    cudaGetSymbolAddress((void**)&os,  g_os);
    cudaGetSymbolAddress((void**)&ot,  g_ot);
    cudaGetSymbolAddress((void**)&wqh, g_wqh);
    cudaGetSymbolAddress((void**)&woh, g_woh);

    cudaFuncSetAttribute(gemm_qkv_kernel,
                         cudaFuncAttributeMaxDynamicSharedMemorySize, G1_SMEM);
    cudaFuncSetAttribute(gemm_out_kernel,
                         cudaFuncAttributeMaxDynamicSharedMemorySize, G2_SMEM);
    cudaFuncSetAttribute(temporal_attn_kernel,
                         cudaFuncAttributeMaxDynamicSharedMemorySize, TSM_BYTES);

    // 0) convert weights to fp16 scratch
    {
        int total = (768 * 256 + 256 * 512) / 2;
        cvt_weights_kernel<<<(total + 255) / 256, 256>>>(w_qkv, w_out, wqh, woh);
    }
    // 1) QKV projection (fp16 mma, A-resident) + fused q/k l2norm
    gemm_qkv_kernel<<<MTOK / 128, 256, G1_SMEM>>>(x, wqh, q, k, v);

    // 2) spatial attention (phase-1 + phase-2 both on tensor cores)
    {
        dim3 grid(B_ * T_, H_);
        spatial_attn_kernel<<<grid, 256>>>(q, k, v, os);
    }
    // 3) temporal attention
    temporal_attn_kernel<<<B_ * N_, 256, TSM_BYTES>>>(q, k, v, ot);

    // 4) output projection + bias (fp16 mma, dual-A concat)
    {
        dim3 grid(2, MTOK / 128);
        gemm_out_kernel<<<grid, 256, G2_SMEM>>>(os, ot, woh, b_out, out);
    }
}

// round 13
// speedup vs baseline: 1.4592x; 1.0160x over previous
#include <cuda_runtime.h>
#include <cuda_fp16.h>
#include <math.h>
#include <stdint.h>

#define B_  4
#define T_  24
#define N_  2048
#define D_  256
#define H_  8
#define HD_ 32
#define MTOK (B_*T_*N_)           // 196608 tokens
#define ELEMS ((size_t)MTOK * D_) // 50,331,648

// Scratch (device globals; allocation-free per harness rules). All fp16.
__device__ __half g_q [ELEMS];
__device__ __half g_k [ELEMS];
__device__ __half g_v [ELEMS];
__device__ __half g_os[ELEMS];
__device__ __half g_ot[ELEMS];
__device__ __half g_wqh[768*256];
__device__ __half g_woh[256*512];

// ---------------------------------------------------------------------------
// helpers
// ---------------------------------------------------------------------------
__device__ __forceinline__ uint32_t smem_u32(const void* p) {
    uint32_t a;
    asm("{ .reg .u64 t; cvta.to.shared.u64 t, %1; cvt.u32.u64 %0, t; }"
        : "=r"(a) : "l"(p));
    return a;
}
__device__ __forceinline__ uint32_t f2h2(float a, float b) {
    __half2 h = __floats2half2_rn(a, b);
    return *(uint32_t*)&h;
}
__device__ __forceinline__ uint2 f4h(float4 v) {
    return make_uint2(f2h2(v.x, v.y), f2h2(v.z, v.w));
}
__device__ __forceinline__ float2 h2f2(uint32_t h) {
    return __half22float2(*(__half2*)&h);
}
__device__ __forceinline__ __half2 u2h2(uint32_t u) { return *(__half2*)&u; }
__device__ __forceinline__ void ldm_x4(uint32_t* r, uint32_t addr) {
    asm volatile("ldmatrix.sync.aligned.m8n8.x4.shared.b16 {%0,%1,%2,%3}, [%4];"
                 : "=r"(r[0]), "=r"(r[1]), "=r"(r[2]), "=r"(r[3]) : "r"(addr));
}
__device__ __forceinline__ void ldm_x4_t(uint32_t* r, uint32_t addr) {
    asm volatile("ldmatrix.sync.aligned.m8n8.x4.trans.shared.b16 {%0,%1,%2,%3}, [%4];"
                 : "=r"(r[0]), "=r"(r[1]), "=r"(r[2]), "=r"(r[3]) : "r"(addr));
}
#define MMA_F16(d, a0, a1, a2, a3, b0, b1)                                    \
    asm volatile("mma.sync.aligned.m16n8k16.row.col.f32.f16.f16.f32 "         \
                 "{%0,%1,%2,%3}, {%4,%5,%6,%7}, {%8,%9}, {%0,%1,%2,%3};"      \
                 : "+f"(d[0]), "+f"(d[1]), "+f"(d[2]), "+f"(d[3])             \
                 : "r"(a0), "r"(a1), "r"(a2), "r"(a3), "r"(b0), "r"(b1))

// Row strides: 80B (chunk tiles) and 528B (resident A). Both ≡16 (mod 128).
#define CH_STRIDE 80
#define CH_BYTES  (128*CH_STRIDE)
#define AR_STRIDE 528
#define AR_BYTES  (128*AR_STRIDE)

// ---------------------------------------------------------------------------
// weight pre-conversion: f32 -> f16 (once per launch)
// ---------------------------------------------------------------------------
__global__ void cvt_weights_kernel(const float* __restrict__ wq,
                                   const float* __restrict__ wo,
                                   __half* __restrict__ wqh,
                                   __half* __restrict__ woh)
{
    int i = blockIdx.x * blockDim.x + threadIdx.x;
    const int NQ = 768 * 256 / 2;
    const int NO = 256 * 512 / 2;
    if (i < NQ) {
        float2 f = *(const float2*)(wq + i * 2);
        *(uint32_t*)(wqh + i * 2) = f2h2(f.x, f.y);
    } else if (i < NQ + NO) {
        int j = i - NQ;
        float2 f = *(const float2*)(wo + j * 2);
        *(uint32_t*)(woh + j * 2) = f2h2(f.x, f.y);
    }
}

// ===========================================================================
// GEMM1 (A-resident, fp16): qkv[M,768] = x[M,256] * w_qkv[768,256]^T
// ===========================================================================
#define G1_SMEM (AR_BYTES + 2*CH_BYTES)   // 88064

__global__ __launch_bounds__(256, 2)
void gemm_qkv_kernel(const float* __restrict__ A, const __half* __restrict__ Bw,
                     __half* __restrict__ outq, __half* __restrict__ outk,
                     __half* __restrict__ outv)
{
    extern __shared__ __align__(16) char smem[];
    const uint32_t sbase = smem_u32(smem);
    const int tid  = threadIdx.x;
    const int lane = tid & 31;
    const int wid  = tid >> 5;
    const int wm   = wid & 1;
    const int wn   = wid >> 1;
    const int m0   = blockIdx.x * 128;

    const int ar = tid >> 1;
    const int ac = tid & 1;
    const int fr = lane & 15;
    const int fc = (lane >> 4) * 16;
    const int r  = lane >> 2;
    const int c2 = (lane & 3) << 1;

    #pragma unroll
    for (int j = 0; j < 8; j++) {
        const float* ap = A + (size_t)(m0 + ar) * 256 + (ac * 8 + j) * 16;
        uint2 h0 = f4h(*(const float4*)(ap + 0));
        uint2 h1 = f4h(*(const float4*)(ap + 4));
        uint2 h2 = f4h(*(const float4*)(ap + 8));
        uint2 h3 = f4h(*(const float4*)(ap + 12));
        char* dst = smem + ar * AR_STRIDE + (ac * 8 + j) * 32;
        *(uint4*)(dst)      = make_uint4(h0.x, h0.y, h1.x, h1.y);
        *(uint4*)(dst + 16) = make_uint4(h2.x, h2.y, h3.x, h3.y);
    }

    uint4 hb0, hb1;
    auto ldgB = [&](int it) {
        const int nt = it >> 3, kt = it & 7;
        const __half* bp = Bw + (size_t)(nt * 128 + ar) * 256 + kt * 32 + ac * 16;
        hb0 = *(const uint4*)(bp);
        hb1 = *(const uint4*)(bp + 8);
    };
    auto stsB = [&](int buf) {
        char* dst = smem + AR_BYTES + buf * CH_BYTES + ar * CH_STRIDE + ac * 32;
        *(uint4*)(dst)      = hb0;
        *(uint4*)(dst + 16) = hb1;
    };

    float acc[4][4][4];
    #pragma unroll
    for (int i = 0; i < 4; i++)
        #pragma unroll
        for (int j = 0; j < 4; j++)
            #pragma unroll
            for (int c = 0; c < 4; c++) acc[i][j][c] = 0.f;

    ldgB(0);
    stsB(0);
    __syncthreads();

    #pragma unroll 1
    for (int it = 0; it < 48; it++) {
        if (it + 1 < 48) ldgB(it + 1);

        {
            const int kt = it & 7;
            const uint32_t abase = sbase + kt * 64;
            const uint32_t bbase = sbase + AR_BYTES + (it & 1) * CH_BYTES;
            #pragma unroll
            for (int s = 0; s < 2; s++) {
                uint32_t af[4][4], bf[2][4];
                #pragma unroll
                for (int mt = 0; mt < 4; mt++) {
                    int row = wm * 64 + mt * 16 + fr;
                    ldm_x4(af[mt], abase + row * AR_STRIDE + s * 32 + fc);
                }
                #pragma unroll
                for (int bi = 0; bi < 2; bi++) {
                    int row = wn * 32 + bi * 16 + fr;
                    ldm_x4(bf[bi], bbase + row * CH_STRIDE + s * 32 + fc);
                }
                #pragma unroll
                for (int mt = 0; mt < 4; mt++)
                    #pragma unroll
                    for (int nt2 = 0; nt2 < 4; nt2++) {
                        int bi = nt2 >> 1, od = nt2 & 1;
                        MMA_F16(acc[mt][nt2],
                                af[mt][0], af[mt][1], af[mt][2], af[mt][3],
                                bf[bi][od], bf[bi][od + 2]);
                    }
            }
        }

        if ((it & 7) == 7) {
            const int n0g = (it >> 3) * 128;
            const int sel = n0g >> 8;

            if (sel < 2) {
                #pragma unroll
                for (int mt = 0; mt < 4; mt++) {
                    float sslo = 0.f, sshi = 0.f;
                    #pragma unroll
                    for (int nt2 = 0; nt2 < 4; nt2++) {
                        sslo = fmaf(acc[mt][nt2][0], acc[mt][nt2][0], sslo);
                        sslo = fmaf(acc[mt][nt2][1], acc[mt][nt2][1], sslo);
                        sshi = fmaf(acc[mt][nt2][2], acc[mt][nt2][2], sshi);
                        sshi = fmaf(acc[mt][nt2][3], acc[mt][nt2][3], sshi);
                    }
                    sslo += __shfl_xor_sync(0xffffffffu, sslo, 1);
                    sslo += __shfl_xor_sync(0xffffffffu, sslo, 2);
                    sshi += __shfl_xor_sync(0xffffffffu, sshi, 1);
                    sshi += __shfl_xor_sync(0xffffffffu, sshi, 2);
                    float slo = 1.f / fmaxf(sqrtf(sslo), 1e-12f);
                    float shi = 1.f / fmaxf(sqrtf(sshi), 1e-12f);
                    #pragma unroll
                    for (int nt2 = 0; nt2 < 4; nt2++) {
                        acc[mt][nt2][0] *= slo; acc[mt][nt2][1] *= slo;
                        acc[mt][nt2][2] *= shi; acc[mt][nt2][3] *= shi;
                    }
                }
            }

            __half* dst = (sel == 0) ? outq : ((sel == 1) ? outk : outv);
            #pragma unroll
            for (int mt = 0; mt < 4; mt++) {
                int m = m0 + wm * 64 + mt * 16 + r;
                #pragma unroll
                for (int nt2 = 0; nt2 < 4; nt2++) {
                    int col = ((n0g + wn * 32 + nt2 * 8 + c2) & 255);
                    float* a = acc[mt][nt2];
                    *(uint32_t*)(dst + (size_t)m * 256 + col)       = f2h2(a[0], a[1]);
                    *(uint32_t*)(dst + (size_t)(m + 8) * 256 + col) = f2h2(a[2], a[3]);
                    a[0] = a[1] = a[2] = a[3] = 0.f;
                }
            }
        }

        if (it + 1 < 48) stsB((it + 1) & 1);
        __syncthreads();
    }
}

// ===========================================================================
// GEMM2 (fp16 in / f32 out): out = [os|ot] * w_out^T + b
// ===========================================================================
#define G2_SMEM (4*CH_BYTES)   // 40960

__global__ __launch_bounds__(256, 2)
void gemm_out_kernel(const __half* __restrict__ A0, const __half* __restrict__ A1,
                     const __half* __restrict__ Bw,
                     const float* __restrict__ bias,
                     float* __restrict__ out)
{
    extern __shared__ __align__(16) char smem[];
    const uint32_t sbase = smem_u32(smem);
    const int tid  = threadIdx.x;
    const int lane = tid & 31;
    const int wid  = tid >> 5;
    const int wm   = wid & 1;
    const int wn   = wid >> 1;
    const int m0   = blockIdx.y * 128;
    const int n0g  = blockIdx.x * 128;

    const int ar = tid >> 1;
    const int ac = tid & 1;
    const int fr = lane & 15;
    const int fc = (lane >> 4) * 16;
    const int r  = lane >> 2;
    const int c2 = (lane & 3) << 1;

    uint4 ua0, ua1, ub0, ub1;
    auto ldg = [&](int kt) {
        const int k0 = kt * 32;
        const __half* Asrc = (k0 < 256) ? A0 : A1;
        const int kc = k0 & 255;
        const __half* ap = Asrc + (size_t)(m0 + ar) * 256 + kc + ac * 16;
        ua0 = *(const uint4*)(ap);
        ua1 = *(const uint4*)(ap + 8);
        const __half* bp = Bw + (size_t)(n0g + ar) * 512 + k0 + ac * 16;
        ub0 = *(const uint4*)(bp);
        ub1 = *(const uint4*)(bp + 8);
    };
    auto sts = [&](int buf) {
        char* da = smem + buf * 2 * CH_BYTES + ar * CH_STRIDE + ac * 32;
        *(uint4*)(da)      = ua0;
        *(uint4*)(da + 16) = ua1;
        char* db = da + CH_BYTES;
        *(uint4*)(db)      = ub0;
        *(uint4*)(db + 16) = ub1;
    };

    float acc[4][4][4];
    #pragma unroll
    for (int i = 0; i < 4; i++)
        #pragma unroll
        for (int j = 0; j < 4; j++)
            #pragma unroll
            for (int c = 0; c < 4; c++) acc[i][j][c] = 0.f;

    ldg(0);
    sts(0);
    __syncthreads();

    #pragma unroll 1
    for (int kt = 0; kt < 16; kt++) {
        if (kt + 1 < 16) ldg(kt + 1);

        {
            const uint32_t abase = sbase + (kt & 1) * 2 * CH_BYTES;
            const uint32_t bbase = abase + CH_BYTES;
            #pragma unroll
            for (int s = 0; s < 2; s++) {
                uint32_t af[4][4], bf[2][4];
                #pragma unroll
                for (int mt = 0; mt < 4; mt++) {
                    int row = wm * 64 + mt * 16 + fr;
                    ldm_x4(af[mt], abase + row * CH_STRIDE + s * 32 + fc);
                }
                #pragma unroll
                for (int bi = 0; bi < 2; bi++) {
                    int row = wn * 32 + bi * 16 + fr;
                    ldm_x4(bf[bi], bbase + row * CH_STRIDE + s * 32 + fc);
                }
                #pragma unroll
                for (int mt = 0; mt < 4; mt++)
                    #pragma unroll
                    for (int nt2 = 0; nt2 < 4; nt2++) {
                        int bi = nt2 >> 1, od = nt2 & 1;
                        MMA_F16(acc[mt][nt2],
                                af[mt][0], af[mt][1], af[mt][2], af[mt][3],
                                bf[bi][od], bf[bi][od + 2]);
                    }
            }
        }

        if (kt + 1 < 16) sts((kt + 1) & 1);
        __syncthreads();
    }

    #pragma unroll
    for (int mt = 0; mt < 4; mt++) {
        int m = m0 + wm * 64 + mt * 16 + r;
        #pragma unroll
        for (int nt = 0; nt < 4; nt++) {
            int n = n0g + wn * 32 + nt * 8 + c2;
            float* a = acc[mt][nt];
            float b0 = bias[n], b1 = bias[n + 1];
            *(float2*)(out + (size_t)m * 256 + n)       = make_float2(a[0] + b0, a[1] + b1);
            *(float2*)(out + (size_t)(m + 8) * 256 + n) = make_float2(a[2] + b0, a[3] + b1);
        }
    }
}

// ---------------------------------------------------------------------------
// Spatial linear attention (attend over N=2048). Block = (bt, h), 8 warps.
// Phase 1: mma via ldmatrix.trans — kvs = k^T [v | 1], kss = column 32.
// Phase 2: mma with B = [kvs^T | kss].
// ---------------------------------------------------------------------------
#define BVS 40   // half stride (80 B) for phase-2 B / q staging rows
#define KST_S 40 // k stage stride (halfs) = 80 B
#define VST_S 56 // v stage stride (halfs) = 112 B
__global__ __launch_bounds__(256)
void spatial_attn_kernel(const __half* __restrict__ q, const __half* __restrict__ k,
                         const __half* __restrict__ v, __half* __restrict__ o)
{
    __shared__ float s_part[8][32][36];
    __shared__ float s_kvs[32][36];
    __shared__ float s_kss[32];
    __shared__ __align__(16) __half s_bv[48 * BVS];

    const int bt = blockIdx.x;
    const int h  = blockIdx.y;
    const int tid = threadIdx.x;
    const int w = tid >> 5, lane = tid & 31;

    const size_t baseBT = (size_t)bt * N_ * D_ + h * HD_;
    const int l0w = w * 256;

    char* wb = (char*)&s_part[w][0][0];
    __half* kst = (__half*)wb;
    __half* vst = (__half*)(wb + 16 * KST_S * 2);
    const uint32_t kstb = smem_u32(kst);
    const uint32_t vstb = smem_u32(vst);

    if (lane < 16) vst[lane * VST_S + 32] = __float2half(1.f);
    __syncwarp();

    const int fr_t = (lane & 7) + ((lane >> 4) & 1) * 8;
    const int fc_t = ((lane >> 3) & 1) * 16;

    float acc1[2][5][4];
    #pragma unroll
    for (int mt = 0; mt < 2; mt++)
        #pragma unroll
        for (int nt = 0; nt < 5; nt++)
            #pragma unroll
            for (int c = 0; c < 4; c++) acc1[mt][nt][c] = 0.f;

    const int crow = lane >> 2;
    const int cq4  = (lane & 3) * 8;

    uint4 kr2[2], vr2[2];
    auto ldgkv = [&](int c16) {
        int l0c = l0w + c16 * 16;
        #pragma unroll
        for (int i = 0; i < 2; i++) {
            int row = l0c + crow + i * 8;
            kr2[i] = *(const uint4*)(k + baseBT + (size_t)row * D_ + cq4);
            vr2[i] = *(const uint4*)(v + baseBT + (size_t)row * D_ + cq4);
        }
    };
    auto stskv = [&]() {
        #pragma unroll
        for (int i = 0; i < 2; i++) {
            int row = crow + i * 8;
            *(uint4*)(kst + row * KST_S + cq4) = kr2[i];
            *(uint4*)(vst + row * VST_S + cq4) = vr2[i];
        }
    };

    ldgkv(0); stskv(); __syncwarp();
    #pragma unroll 1
    for (int c16 = 0; c16 < 16; c16++) {
        if (c16 + 1 < 16) ldgkv(c16 + 1);

        uint32_t afr[2][4], bfr[3][4];
        ldm_x4_t(afr[0], kstb + fr_t * (KST_S * 2) + fc_t);
        ldm_x4_t(afr[1], kstb + fr_t * (KST_S * 2) + 32 + fc_t);
        ldm_x4_t(bfr[0], vstb + fr_t * (VST_S * 2) + fc_t);
        ldm_x4_t(bfr[1], vstb + fr_t * (VST_S * 2) + 32 + fc_t);
        ldm_x4_t(bfr[2], vstb + fr_t * (VST_S * 2) + 64 + fc_t);

        #pragma unroll
        for (int mt = 0; mt < 2; mt++)
            #pragma unroll
            for (int nt = 0; nt < 5; nt++) {
                int bn = nt >> 1, od = nt & 1;
                MMA_F16(acc1[mt][nt],
                        afr[mt][0], afr[mt][1], afr[mt][2], afr[mt][3],
                        bfr[bn][od], bfr[bn][od + 2]);
            }

        if (c16 + 1 < 16) {
            __syncwarp();
            stskv();
        }
        __syncwarp();
    }

    {
        const int r = lane >> 2;
        const int c2l = (lane & 3) << 1;
        #pragma unroll
        for (int mt = 0; mt < 2; mt++) {
            #pragma unroll
            for (int nt = 0; nt < 4; nt++) {
                *(float2*)&s_part[w][mt*16 + r][nt*8 + c2l] =
                    make_float2(acc1[mt][nt][0], acc1[mt][nt][1]);
                *(float2*)&s_part[w][mt*16 + r + 8][nt*8 + c2l] =
                    make_float2(acc1[mt][nt][2], acc1[mt][nt][3]);
            }
            if (c2l == 0) {
                s_part[w][mt*16 + r][32]     = acc1[mt][4][0];
                s_part[w][mt*16 + r + 8][32] = acc1[mt][4][2];
            }
        }
    }
    __syncthreads();

    {
        int m = tid >> 3, dd = (tid & 7) * 4;
        float4 s = make_float4(0.f, 0.f, 0.f, 0.f);
        #pragma unroll
        for (int wi = 0; wi < 8; wi++) {
            float4 p = *(const float4*)&s_part[wi][m][dd];
            s.x += p.x; s.y += p.y; s.z += p.z; s.w += p.w;
        }
        *(float4*)&s_kvs[m][dd] = s;
        if (tid < 32) {
            float s2 = 0.f;
            #pragma unroll
            for (int wi = 0; wi < 8; wi++) s2 += s_part[wi][tid][32];
            s_kss[tid] = s2;
        }
    }
    __syncthreads();

    for (int idx = tid; idx < 33 * 32; idx += 256) {
        int nn = idx >> 5, m = idx & 31;
        float val = (nn < 32) ? s_kvs[m][nn] : s_kss[m];
        s_bv[nn * BVS + m] = __float2half(val);
    }
    __syncthreads();

    const int fr = lane & 15;
    const int fc = (lane >> 4) * 16;
    const int r  = lane >> 2;
    const int c2 = (lane & 3) << 1;

    const uint32_t bvb = smem_u32(s_bv);
    uint32_t bf[3][2][4];
    #pragma unroll
    for (int bn = 0; bn < 3; bn++)
        #pragma unroll
        for (int s = 0; s < 2; s++)
            ldm_x4(bf[bn][s], bvb + (bn * 16 + fr) * (BVS * 2) + s * 32 + fc);

    __half* qs_h = (__half*)&s_part[w][0][0];
    const uint32_t qsb = smem_u32(qs_h);

    for (int c = 0; c < 8; c++) {
        const int l0 = l0w + c * 32;
        #pragma unroll
        for (int i2 = 0; i2 < 4; i2++) {
            int idx = lane + i2 * 32;
            int rr = idx >> 2, f = idx & 3;
            *(uint4*)(qs_h + rr * BVS + f * 8) =
                *(const uint4*)(q + baseBT + (size_t)(l0 + rr) * D_ + f * 8);
        }
        __syncwarp();

        uint32_t af[2][2][4];
        #pragma unroll
        for (int mt = 0; mt < 2; mt++)
            #pragma unroll
            for (int s = 0; s < 2; s++)
                ldm_x4(af[mt][s], qsb + (mt * 16 + fr) * (BVS * 2) + s * 32 + fc);

        float acc[2][5][4];
        #pragma unroll
        for (int mt = 0; mt < 2; mt++)
            #pragma unroll
            for (int nt = 0; nt < 5; nt++)
                #pragma unroll
                for (int cc = 0; cc < 4; cc++) acc[mt][nt][cc] = 0.f;

        #pragma unroll
        for (int mt = 0; mt < 2; mt++)
            #pragma unroll
            for (int nt = 0; nt < 5; nt++) {
                int bn = nt >> 1, od = nt & 1;
                #pragma unroll
                for (int s = 0; s < 2; s++)
                    MMA_F16(acc[mt][nt],
                            af[mt][s][0], af[mt][s][1], af[mt][s][2], af[mt][s][3],
                            bf[bn][s][od], bf[bn][s][od + 2]);
            }

        #pragma unroll
        for (int mt = 0; mt < 2; mt++) {
            float dlo = __shfl_sync(0xffffffffu, acc[mt][4][0], lane & 28);
            float dhi = __shfl_sync(0xffffffffu, acc[mt][4][2], lane & 28);
            float ilo = 1.f / fmaxf(dlo + (float)N_, 1e-5f);
            float ihi = 1.f / fmaxf(dhi + (float)N_, 1e-5f);
            int tlo = l0 + mt * 16 + r;
            int thi = tlo + 8;
            #pragma unroll
            for (int nt = 0; nt < 4; nt++) {
                int d = nt * 8 + c2;
                float2 vl = h2f2(*(const uint32_t*)(v + baseBT + (size_t)tlo * D_ + d));
                float2 vh = h2f2(*(const uint32_t*)(v + baseBT + (size_t)thi * D_ + d));
                float r0 = (acc[mt][nt][0] + (float)N_ * vl.x) * ilo;
                float r1 = (acc[mt][nt][1] + (float)N_ * vl.y) * ilo;
                float r2 = (acc[mt][nt][2] + (float)N_ * vh.x) * ihi;
                float r3 = (acc[mt][nt][3] + (float)N_ * vh.y) * ihi;
                *(uint32_t*)(o + baseBT + (size_t)tlo * D_ + d) = f2h2(r0, r1);
                *(uint32_t*)(o + baseBT + (size_t)thi * D_ + d) = f2h2(r2, r3);
            }
        }
        __syncwarp();
    }
}

// ---------------------------------------------------------------------------
// Temporal linear attention (attend over T=24). Block = (b, n), warp = head.
// Phase 1: mma via ldmatrix.trans with operands swapped:
//   kvs^T = [v|1]^T k   (A = v-stage, B = k-stage, k-dim = tokens padded to 32,
//   pad rows zeroed in BOTH stages). Output acc rows = d|kss, cols = mu ->
//   stored directly as the phase-2 B half matrix (no transpose spill).
// Phase 2: mma (unchanged).
// ---------------------------------------------------------------------------
#define TKS 40                 // temporal k-stage stride (halfs), 80 B
#define TVS 56                 // temporal v-stage stride (halfs), 112 B
#define TPH 3200               // halfs per head (stages aliased under bv+q)
#define TSM_BYTES (8 * TPH * 2)            // 51200
__global__ __launch_bounds__(256)
void temporal_attn_kernel(const __half* __restrict__ q, const __half* __restrict__ k,
                          const __half* __restrict__ v, __half* __restrict__ o)
{
    extern __shared__ __align__(16) __half smh[];
    const int bn = blockIdx.x;
    const int b = bn >> 11;
    const int n = bn & 2047;
    const int tid = threadIdx.x;
    const int h = tid >> 5, lane = tid & 31;

    __half* hb   = smh + h * TPH;
    __half* kst  = hb;                 // 32 x TKS (phase-1)
    __half* vst  = hb + 32 * TKS;      // 32 x TVS (phase-1)
    __half* bv_h = hb;                 // 48 x BVS (phase-2, aliases kst/vst)
    __half* qs_h = hb + 48 * BVS;      // 32 x BVS (phase-2)

    const size_t base = ((size_t)b * T_ * N_ + n) * D_ + h * HD_;
    const size_t sT = (size_t)N_ * D_;

    const uint32_t kstb = smem_u32(kst);
    const uint32_t vstb = smem_u32(vst);

    // zero pad token rows 24..31 in BOTH stages (40 + 56 = 96 uint4, 3/lane)
    {
        const uint4 z = make_uint4(0, 0, 0, 0);
        #pragma unroll
        for (int i = 0; i < 3; i++) {
            int idx = lane + i * 32;            // 0..95
            if (idx < 40) {
                int rr = idx / 5, cc = idx % 5;
                *(uint4*)(kst + (24 + rr) * TKS + cc * 8) = z;
            } else {
                int j = idx - 40;
                int rr = j / 7, cc = j % 7;
                *(uint4*)(vst + (24 + rr) * TVS + cc * 8) = z;
            }
        }
    }
    // stage k, v (24 token rows x 32 halfs)
    #pragma unroll
    for (int i = 0; i < 3; i++) {
        int idx = lane + i * 32;                // 0..95
        int t = idx >> 2, f = idx & 3;
        *(uint4*)(kst + t * TKS + f * 8) =
            *(const uint4*)(k + base + (size_t)t * sT + f * 8);
        *(uint4*)(vst + t * TVS + f * 8) =
            *(const uint4*)(v + base + (size_t)t * sT + f * 8);
    }
    // ones column for kss (real token rows only; pad rows already zero)
    if (lane < 24) vst[lane * TVS + 32] = __float2half(1.f);
    __syncwarp();

    const int fr_t = (lane & 7) + ((lane >> 4) & 1) * 8;
    const int fc_t = ((lane >> 3) & 1) * 16;

    float acc1[3][4][4];
    #pragma unroll
    for (int mi = 0; mi < 3; mi++)
        #pragma unroll
        for (int ni = 0; ni < 4; ni++)
            #pragma unroll
            for (int c = 0; c < 4; c++) acc1[mi][ni][c] = 0.f;

    #pragma unroll
    for (int s = 0; s < 2; s++) {
        uint32_t afr[3][4], bfr[2][4];
        #pragma unroll
        for (int mi = 0; mi < 3; mi++)
            ldm_x4_t(afr[mi], vstb + (s * 16 + fr_t) * (TVS * 2) + mi * 32 + fc_t);
        #pragma unroll
        for (int bi = 0; bi < 2; bi++)
            ldm_x4_t(bfr[bi], kstb + (s * 16 + fr_t) * (TKS * 2) + bi * 32 + fc_t);
        #pragma unroll
        for (int mi = 0; mi < 3; mi++)
            #pragma unroll
            for (int ni = 0; ni < 4; ni++) {
                int bi = ni >> 1, od = ni & 1;
                MMA_F16(acc1[mi][ni],
                        afr[mi][0], afr[mi][1], afr[mi][2], afr[mi][3],
                        bfr[bi][od], bfr[bi][od + 2]);
            }
    }
    __syncwarp();

    const int r  = lane >> 2;
    const int c2 = (lane & 3) << 1;

    // store kvs^T|kss directly as phase-2 B (rows = d|kss, cols = mu)
    #pragma unroll
    for (int mi = 0; mi < 3; mi++)
        #pragma unroll
        for (int ni = 0; ni < 4; ni++) {
            *(uint32_t*)(bv_h + (mi * 16 + r) * BVS + ni * 8 + c2) =
                f2h2(acc1[mi][ni][0], acc1[mi][ni][1]);
            *(uint32_t*)(bv_h + (mi * 16 + r + 8) * BVS + ni * 8 + c2) =
                f2h2(acc1[mi][ni][2], acc1[mi][ni][3]);
        }
    // stage q (24 rows x 32 halfs)
    #pragma unroll
    for (int i = 0; i < 3; i++) {
        int idx = lane + i * 32;
        int t = idx >> 2, f = idx & 3;
        *(uint4*)(qs_h + t * BVS + f * 8) =
            *(const uint4*)(q + base + (size_t)t * sT + f * 8);
    }
    __syncwarp();

    const int fr = lane & 15;
    const int fc = (lane >> 4) * 16;

    const uint32_t bvb = smem_u32(bv_h);
    const uint32_t qsb = smem_u32(qs_h);

    uint32_t bf[3][2][4], af[2][2][4];
    #pragma unroll
    for (int bn2 = 0; bn2 < 3; bn2++)
        #pragma unroll
        for (int s = 0; s < 2; s++)
            ldm_x4(bf[bn2][s], bvb + (bn2 * 16 + fr) * (BVS * 2) + s * 32 + fc);
    #pragma unroll
    for (int mt = 0; mt < 2; mt++)
        #pragma unroll
        for (int s = 0; s < 2; s++)
            ldm_x4(af[mt][s], qsb + (mt * 16 + fr) * (BVS * 2) + s * 32 + fc);

    float acc[2][5][4];
    #pragma unroll
    for (int mt = 0; mt < 2; mt++)
        #pragma unroll
        for (int nt = 0; nt < 5; nt++)
            #pragma unroll
            for (int cc = 0; cc < 4; cc++) acc[mt][nt][cc] = 0.f;

    #pragma unroll
    for (int mt = 0; mt < 2; mt++)
        #pragma unroll
        for (int nt = 0; nt < 5; nt++) {
            int bn2 = nt >> 1, od = nt & 1;
            #pragma unroll
            for (int s = 0; s < 2; s++)
                MMA_F16(acc[mt][nt],
                        af[mt][s][0], af[mt][s][1], af[mt][s][2], af[mt][s][3],
                        bf[bn2][s][od], bf[bn2][s][od + 2]);
        }

    #pragma unroll
    for (int mt = 0; mt < 2; mt++) {
        float dlo = __shfl_sync(0xffffffffu, acc[mt][4][0], lane & 28);
        float dhi = __shfl_sync(0xffffffffu, acc[mt][4][2], lane & 28);
        float ilo = 1.f / fmaxf(dlo + (float)T_, 1e-5f);
        float ihi = 1.f / fmaxf(dhi + (float)T_, 1e-5f);
        int tlo = mt * 16 + r;
        int thi = tlo + 8;
        bool hiv = (thi < T_);
        #pragma unroll
        for (int nt = 0; nt < 4; nt++) {
            int d = nt * 8 + c2;
            float2 vl = h2f2(*(const uint32_t*)(v + base + (size_t)tlo * sT + d));
            float r0 = (acc[mt][nt][0] + (float)T_ * vl.x) * ilo;
            float r1 = (acc[mt][nt][1] + (float)T_ * vl.y) * ilo;
            *(uint32_t*)(o + base + (size_t)tlo * sT + d) = f2h2(r0, r1);
            if (hiv) {
                float2 vh = h2f2(*(const uint32_t*)(v + base + (size_t)thi * sT + d));
                float r2 = (acc[mt][nt][2] + (float)T_ * vh.x) * ihi;
                float r3 = (acc[mt][nt][3] + (float)T_ * vh.y) * ihi;
                *(uint32_t*)(o + base + (size_t)thi * sT + d) = f2h2(r2, r3);
            }
        }
    }
}

// ---------------------------------------------------------------------------
extern "C" void kernel_launch(void* const* d_in, const int* in_sizes, int n_in,
                              void* d_out, int out_size)
{
    const float* x     = (const float*)d_in[0];
    const float* w_qkv = (const float*)d_in[1];
    const float* w_out = (const float*)d_in[2];
    const float* b_out = (const float*)d_in[3];
    float* out = (float*)d_out;

    __half *q, *k, *v, *os, *ot, *wqh, *woh;
    cudaGetSymbolAddress((void**)&q,   g_q);
    cudaGetSymbolAddress((void**)&k,   g_k);
    cudaGetSymbolAddress((void**)&v,   g_v);
    cudaGetSymbolAddress((void**)&os,  g_os);
    cudaGetSymbolAddress((void**)&ot,  g_ot);
    cudaGetSymbolAddress((void**)&wqh, g_wqh);
    cudaGetSymbolAddress((void**)&woh, g_woh);

    cudaFuncSetAttribute(gemm_qkv_kernel,
                         cudaFuncAttributeMaxDynamicSharedMemorySize, G1_SMEM);
    cudaFuncSetAttribute(gemm_out_kernel,
                         cudaFuncAttributeMaxDynamicSharedMemorySize, G2_SMEM);
    cudaFuncSetAttribute(temporal_attn_kernel,
                         cudaFuncAttributeMaxDynamicSharedMemorySize, TSM_BYTES);

    // 0) convert weights to fp16 scratch
    {
        int total = (768 * 256 + 256 * 512) / 2;
        cvt_weights_kernel<<<(total + 255) / 256, 256>>>(w_qkv, w_out, wqh, woh);
    }
    // 1) QKV projection (fp16 mma, A-resident) + fused q/k l2norm
    gemm_qkv_kernel<<<MTOK / 128, 256, G1_SMEM>>>(x, wqh, q, k, v);

    // 2) spatial attention (both phases on tensor cores)
    {
        dim3 grid(B_ * T_, H_);
        spatial_attn_kernel<<<grid, 256>>>(q, k, v, os);
    }
    // 3) temporal attention (both phases on tensor cores)
    temporal_attn_kernel<<<B_ * N_, 256, TSM_BYTES>>>(q, k, v, ot);

    // 4) output projection + bias (fp16 mma, dual-A concat)
    {
        dim3 grid(2, MTOK / 128);
        gemm_out_kernel<<<grid, 256, G2_SMEM>>>(os, ot, woh, b_out, out);
    }
}